// round 1
// baseline (speedup 1.0000x reference)
#include <cuda_runtime.h>

// Problem constants
#define B_  4
#define S_  1024
#define D_  1024
#define H_  16
#define HD_ 64
#define M_  (B_ * S_)     // 4096 rows (b,s flattened)

// ---------------------------------------------------------------------------
// Scratch (device globals: no allocation allowed)
// ---------------------------------------------------------------------------
__device__ __align__(16) float g_Q  [(size_t)M_ * D_];      // 16 MB, [B,S,H,HD] row-major
__device__ __align__(16) float g_K  [(size_t)M_ * D_];
__device__ __align__(16) float g_V  [(size_t)M_ * D_];
__device__ __align__(16) float g_C  [(size_t)M_ * D_];      // attention context
__device__ __align__(16) float g_Hid[(size_t)M_ * 2 * D_];  // 32 MB, MLP hidden

// ---------------------------------------------------------------------------
// SGEMM: C[m,n] = sum_k A[m,k] * B[n,k] + bias[n]   (both row-major, "NT")
// 128x128 block tile, K-tile 8, 256 threads, 8x8 per-thread microtile.
// M,N multiples of 128; K multiple of 8 (all true for our shapes).
// ---------------------------------------------------------------------------
template <bool RELU>
__global__ __launch_bounds__(256)
void sgemm_nt(const float* __restrict__ A, const float* __restrict__ Bm,
              const float* __restrict__ bias, float* __restrict__ C,
              int M, int N, int K)
{
    __shared__ float As[8][128];
    __shared__ float Bs[8][128];

    const int tid = threadIdx.x;
    const int bn  = blockIdx.x;
    const int bm  = blockIdx.y;
    const int tx  = tid & 15;        // 0..15
    const int ty  = tid >> 4;        // 0..15
    const int lr  = tid >> 1;        // 0..127 : tile row to load
    const int lk  = (tid & 1) * 4;   // 0 or 4 : k sub-offset

    const float* Ag = A  + (size_t)(bm * 128 + lr) * K + lk;
    const float* Bg = Bm + (size_t)(bn * 128 + lr) * K + lk;

    float acc[8][8];
#pragma unroll
    for (int i = 0; i < 8; i++)
#pragma unroll
        for (int j = 0; j < 8; j++) acc[i][j] = 0.f;

    for (int kt = 0; kt < K; kt += 8) {
        const float4 av = *(const float4*)(Ag + kt);
        const float4 bv = *(const float4*)(Bg + kt);
        __syncthreads();   // previous compute done before overwrite
        As[lk + 0][lr] = av.x; As[lk + 1][lr] = av.y;
        As[lk + 2][lr] = av.z; As[lk + 3][lr] = av.w;
        Bs[lk + 0][lr] = bv.x; Bs[lk + 1][lr] = bv.y;
        Bs[lk + 2][lr] = bv.z; Bs[lk + 3][lr] = bv.w;
        __syncthreads();

#pragma unroll
        for (int k = 0; k < 8; k++) {
            float a[8], b[8];
            *(float4*)&a[0] = *(const float4*)&As[k][ty * 4];
            *(float4*)&a[4] = *(const float4*)&As[k][64 + ty * 4];
            *(float4*)&b[0] = *(const float4*)&Bs[k][tx * 4];
            *(float4*)&b[4] = *(const float4*)&Bs[k][64 + tx * 4];
#pragma unroll
            for (int i = 0; i < 8; i++)
#pragma unroll
                for (int j = 0; j < 8; j++)
                    acc[i][j] += a[i] * b[j];
        }
    }

    // Epilogue: bias (+ReLU), vectorized stores
#pragma unroll
    for (int i = 0; i < 8; i++) {
        const int m = bm * 128 + ((i < 4) ? (ty * 4 + i) : (64 + ty * 4 + (i - 4)));
#pragma unroll
        for (int jh = 0; jh < 2; jh++) {
            const int n0 = bn * 128 + jh * 64 + tx * 4;
            float4 o;
            o.x = acc[i][jh * 4 + 0] + bias[n0 + 0];
            o.y = acc[i][jh * 4 + 1] + bias[n0 + 1];
            o.z = acc[i][jh * 4 + 2] + bias[n0 + 2];
            o.w = acc[i][jh * 4 + 3] + bias[n0 + 3];
            if (RELU) {
                o.x = fmaxf(o.x, 0.f); o.y = fmaxf(o.y, 0.f);
                o.z = fmaxf(o.z, 0.f); o.w = fmaxf(o.w, 0.f);
            }
            *(float4*)&C[(size_t)m * N + n0] = o;
        }
    }
}

// ---------------------------------------------------------------------------
// Flash attention (fp32, online softmax).
// Grid: (S/64 query tiles, B*H). 256 threads.
// Q,K,V are [B,S,H,HD] row-major (= [4096,1024]); output ctx same layout.
// Per-thread: 4 query rows (ty*4+i) x 4 key/value cols (tx + 16*j).
// Smem: Qs[64][68], Ks[64][68] row-major, Vt[64][68] transposed (d-major),
//       Ps[64][68] probabilities.
// ---------------------------------------------------------------------------
#define AST 68
#define ATTN_SMEM_BYTES (4 * 64 * AST * 4 + 3 * 64 * 4)

__global__ __launch_bounds__(256)
void attn_kernel(const float* __restrict__ Q, const float* __restrict__ K,
                 const float* __restrict__ V, const int* __restrict__ mask,
                 float* __restrict__ O)
{
    extern __shared__ float sm[];
    float* Qs   = sm;                 // [64][AST]
    float* Ks   = Qs + 64 * AST;      // [64][AST]  (key rows, d cols)
    float* Vt   = Ks + 64 * AST;      // [64][AST]  (d rows, key cols) TRANSPOSED
    float* Ps   = Vt + 64 * AST;      // [64][AST]
    float* mrow = Ps + 64 * AST;      // [64]
    float* lrow = mrow + 64;          // [64]
    float* arow = lrow + 64;          // [64]

    const int tid = threadIdx.x;
    const int qt  = blockIdx.x;
    const int bh  = blockIdx.y;
    const int b   = bh >> 4;
    const int h   = bh & 15;
    const int q0  = qt * 64;
    const int tx  = tid & 15;
    const int ty  = tid >> 4;

    const size_t headoff = (size_t)b * S_ * D_ + (size_t)h * HD_;
    const float* Qb = Q + headoff;
    const float* Kb = K + headoff;
    const float* Vb = V + headoff;

    // Load Q tile: each thread loads one quarter-row (16 floats)
    {
        const int r  = tid >> 2;
        const int c0 = (tid & 3) * 16;
        const float* src = Qb + (size_t)(q0 + r) * D_ + c0;
#pragma unroll
        for (int i = 0; i < 4; i++)
            *(float4*)&Qs[r * AST + c0 + i * 4] = *(const float4*)(src + i * 4);
    }
    if (tid < 64) { mrow[tid] = -1e30f; lrow[tid] = 0.f; }

    float acc[4][4];
#pragma unroll
    for (int i = 0; i < 4; i++)
#pragma unroll
        for (int j = 0; j < 4; j++) acc[i][j] = 0.f;

    for (int kt = 0; kt < S_ / 64; kt++) {
        const int k0 = kt * 64;
        __syncthreads();   // Q visible (iter 0) / prior PV done before overwrite
        {
            const int r  = tid >> 2;
            const int c0 = (tid & 3) * 16;
            const float* ksrc = Kb + (size_t)(k0 + r) * D_ + c0;
            const float* vsrc = Vb + (size_t)(k0 + r) * D_ + c0;
#pragma unroll
            for (int i = 0; i < 4; i++) {
                *(float4*)&Ks[r * AST + c0 + i * 4] = *(const float4*)(ksrc + i * 4);
                const float4 vv = *(const float4*)(vsrc + i * 4);
                Vt[(c0 + i * 4 + 0) * AST + r] = vv.x;
                Vt[(c0 + i * 4 + 1) * AST + r] = vv.y;
                Vt[(c0 + i * 4 + 2) * AST + r] = vv.z;
                Vt[(c0 + i * 4 + 3) * AST + r] = vv.w;
            }
        }
        __syncthreads();

        // Scores S = Q K^T (vectorized over d)
        float s[4][4];
#pragma unroll
        for (int i = 0; i < 4; i++)
#pragma unroll
            for (int j = 0; j < 4; j++) s[i][j] = 0.f;

#pragma unroll
        for (int d4 = 0; d4 < 16; d4++) {
            float4 q4[4], k4[4];
#pragma unroll
            for (int i = 0; i < 4; i++)
                q4[i] = *(const float4*)&Qs[(ty * 4 + i) * AST + d4 * 4];
#pragma unroll
            for (int j = 0; j < 4; j++)
                k4[j] = *(const float4*)&Ks[(tx + 16 * j) * AST + d4 * 4];
#pragma unroll
            for (int i = 0; i < 4; i++)
#pragma unroll
                for (int j = 0; j < 4; j++)
                    s[i][j] += q4[i].x * k4[j].x + q4[i].y * k4[j].y +
                               q4[i].z * k4[j].z + q4[i].w * k4[j].w;
        }

        // Scale + mask, stage into Ps
        const int* mb = mask + ((size_t)b * S_ + q0) * S_ + k0;
#pragma unroll
        for (int i = 0; i < 4; i++)
#pragma unroll
            for (int j = 0; j < 4; j++) {
                float v = s[i][j] * 0.125f;   // 1/sqrt(64)
                if (mb[(size_t)(ty * 4 + i) * S_ + tx + 16 * j] == 0) v = -1e8f;
                Ps[(ty * 4 + i) * AST + tx + 16 * j] = v;
            }
        __syncthreads();

        // Online softmax: one thread per query row
        if (tid < 64) {
            const int r = tid;
            const float mprev = mrow[r];
            float mx = mprev;
#pragma unroll 8
            for (int c = 0; c < 64; c++) mx = fmaxf(mx, Ps[r * AST + c]);
            const float alpha = __expf(mprev - mx);
            float sum = 0.f;
#pragma unroll 8
            for (int c = 0; c < 64; c++) {
                const float e = __expf(Ps[r * AST + c] - mx);
                Ps[r * AST + c] = e;
                sum += e;
            }
            lrow[r] = lrow[r] * alpha + sum;
            mrow[r] = mx;
            arow[r] = alpha;
        }
        __syncthreads();

        // Rescale + accumulate PV (vectorized over kk via transposed V)
        float al[4];
#pragma unroll
        for (int i = 0; i < 4; i++) al[i] = arow[ty * 4 + i];
#pragma unroll
        for (int i = 0; i < 4; i++)
#pragma unroll
            for (int j = 0; j < 4; j++) acc[i][j] *= al[i];

#pragma unroll
        for (int k4 = 0; k4 < 16; k4++) {
            float4 p4[4], v4[4];
#pragma unroll
            for (int i = 0; i < 4; i++)
                p4[i] = *(const float4*)&Ps[(ty * 4 + i) * AST + k4 * 4];
#pragma unroll
            for (int j = 0; j < 4; j++)
                v4[j] = *(const float4*)&Vt[(tx + 16 * j) * AST + k4 * 4];
#pragma unroll
            for (int i = 0; i < 4; i++)
#pragma unroll
                for (int j = 0; j < 4; j++)
                    acc[i][j] += p4[i].x * v4[j].x + p4[i].y * v4[j].y +
                                 p4[i].z * v4[j].z + p4[i].w * v4[j].w;
        }
    }

    // Finalize: divide by l, write ctx in [B,S,H,HD] layout
#pragma unroll
    for (int i = 0; i < 4; i++) {
        const int r = ty * 4 + i;
        const float inv = 1.0f / lrow[r];
        const size_t rowoff = (size_t)(b * S_ + q0 + r) * D_ + (size_t)h * HD_;
#pragma unroll
        for (int j = 0; j < 4; j++)
            O[rowoff + tx + 16 * j] = acc[i][j] * inv;
    }
}

// ---------------------------------------------------------------------------
// Launch
// Inputs (metadata order): x, Wq, bq, Wk, bk, Wv, bv, W1, b1, W2, b2, mask
// ---------------------------------------------------------------------------
extern "C" void kernel_launch(void* const* d_in, const int* in_sizes, int n_in,
                              void* d_out, int out_size)
{
    const float* x    = (const float*)d_in[0];
    const float* Wq   = (const float*)d_in[1];
    const float* bq   = (const float*)d_in[2];
    const float* Wk   = (const float*)d_in[3];
    const float* bk   = (const float*)d_in[4];
    const float* Wv   = (const float*)d_in[5];
    const float* bv   = (const float*)d_in[6];
    const float* W1   = (const float*)d_in[7];
    const float* b1   = (const float*)d_in[8];
    const float* W2   = (const float*)d_in[9];
    const float* b2   = (const float*)d_in[10];
    const int*   mask = (const int*)d_in[11];
    float*       out  = (float*)d_out;

    float *Qp, *Kp, *Vp, *Cp, *Hp;
    cudaGetSymbolAddress((void**)&Qp, g_Q);
    cudaGetSymbolAddress((void**)&Kp, g_K);
    cudaGetSymbolAddress((void**)&Vp, g_V);
    cudaGetSymbolAddress((void**)&Cp, g_C);
    cudaGetSymbolAddress((void**)&Hp, g_Hid);

    cudaFuncSetAttribute(attn_kernel,
                         cudaFuncAttributeMaxDynamicSharedMemorySize,
                         ATTN_SMEM_BYTES);

    const dim3 blk(256);

    // QKV projections: [4096,1024] = x[4096,1024] @ W^T[1024,1024]
    sgemm_nt<false><<<dim3(D_ / 128, M_ / 128), blk>>>(x, Wq, bq, Qp, M_, D_, D_);
    sgemm_nt<false><<<dim3(D_ / 128, M_ / 128), blk>>>(x, Wk, bk, Kp, M_, D_, D_);
    sgemm_nt<false><<<dim3(D_ / 128, M_ / 128), blk>>>(x, Wv, bv, Vp, M_, D_, D_);

    // Attention: grid (16 q-tiles, 64 head-batches)
    attn_kernel<<<dim3(S_ / 64, B_ * H_), blk, ATTN_SMEM_BYTES>>>(Qp, Kp, Vp, mask, Cp);

    // MLP: hidden = relu(ctx @ W1^T + b1) ; out = hidden @ W2^T + b2
    sgemm_nt<true ><<<dim3(2 * D_ / 128, M_ / 128), blk>>>(Cp, W1, b1, Hp, M_, 2 * D_, D_);
    sgemm_nt<false><<<dim3(D_ / 128, M_ / 128), blk>>>(Hp, W2, b2, out, M_, D_, 2 * D_);
}

// round 2
// speedup vs baseline: 1.4451x; 1.4451x over previous
#include <cuda_runtime.h>
#include <stdint.h>

// Problem constants
#define B_  4
#define S_  1024
#define D_  1024
#define H_  16
#define HD_ 64
#define M_  (B_ * S_)     // 4096 rows (b,s flattened)

// ---------------------------------------------------------------------------
// Scratch (device globals: no allocation allowed)
// ---------------------------------------------------------------------------
__device__ __align__(16) float g_Q  [(size_t)M_ * D_];
__device__ __align__(16) float g_K  [(size_t)M_ * D_];
__device__ __align__(16) float g_V  [(size_t)M_ * D_];
__device__ __align__(16) float g_C  [(size_t)M_ * D_];
__device__ __align__(16) float g_Hid[(size_t)M_ * 2 * D_];

// ---------------------------------------------------------------------------
// TF32 helpers
// ---------------------------------------------------------------------------
__device__ __forceinline__ float to_tf32(float x) {
    uint32_t u;
    asm("cvt.rna.tf32.f32 %0, %1;" : "=r"(u) : "f"(x));
    return __uint_as_float(u);
}

__device__ __forceinline__ void mma_tf32(float* c, const float* a, const float* b) {
    asm volatile(
        "mma.sync.aligned.m16n8k8.row.col.f32.tf32.tf32.f32 "
        "{%0,%1,%2,%3}, {%4,%5,%6,%7}, {%8,%9}, {%0,%1,%2,%3};\n"
        : "+f"(c[0]), "+f"(c[1]), "+f"(c[2]), "+f"(c[3])
        : "r"(__float_as_uint(a[0])), "r"(__float_as_uint(a[1])),
          "r"(__float_as_uint(a[2])), "r"(__float_as_uint(a[3])),
          "r"(__float_as_uint(b[0])), "r"(__float_as_uint(b[1])));
}

// ---------------------------------------------------------------------------
// Tensor-core GEMM (tf32): C[m,n] = sum_k A[m,k]*B[n,k] + bias[n]  ("NT")
// Block tile 128x128, K-tile 16, 256 threads (8 warps, 2x4), warp tile 64x32.
// Fragments loaded as conflict-free LDS.64 via k-permutation:
//   logical c<4  <-> phys 2c ;  logical c>=4 <-> phys 2(c-4)+1
// Smem row stride 24 floats => fragment LDS.64 is bank-conflict-free.
// Double-buffered smem (2 stages x (A 12KB + B 12KB) = 48KB) + reg prefetch.
// Requires: M%128==0, N%128==0, K%16==0.
// ---------------------------------------------------------------------------
#define ASTR 24
#define STAGE_FLOATS (128 * ASTR)          // 3072 floats per matrix per stage
#define GEMM_SMEM_BYTES (4 * STAGE_FLOATS * 4)  // 49152

template <bool RELU>
__global__ __launch_bounds__(256)
void gemm_tc(const float* __restrict__ A, const float* __restrict__ Bm,
             const float* __restrict__ bias, float* __restrict__ C,
             int M, int N, int K)
{
    extern __shared__ float sm[];
    // layout: [A stage0][A stage1][B stage0][B stage1]
    float* Abuf[2] = { sm, sm + STAGE_FLOATS };
    float* Bbuf[2] = { sm + 2 * STAGE_FLOATS, sm + 3 * STAGE_FLOATS };

    const int tid  = threadIdx.x;
    const int lane = tid & 31;
    const int wid  = tid >> 5;
    const int wm   = wid >> 2;          // warp row  (0..1) -> 64 rows
    const int wn   = wid & 3;           // warp col  (0..3) -> 32 cols
    const int grp  = lane >> 2;         // 0..7
    const int qid  = lane & 3;          // 0..3

    const int bm = blockIdx.y * 128;
    const int bn = blockIdx.x * 128;

    // G2S job mapping: 2 float4 rows-of-16 per thread per matrix
    const int r0 = tid >> 2;            // 0..63
    const int c4 = (tid & 3) * 4;       // 0,4,8,12
    const float* Ag0 = A  + (size_t)(bm + r0)      * K + c4;
    const float* Ag1 = A  + (size_t)(bm + r0 + 64) * K + c4;
    const float* Bg0 = Bm + (size_t)(bn + r0)      * K + c4;
    const float* Bg1 = Bm + (size_t)(bn + r0 + 64) * K + c4;

    float acc[4][4][4];
#pragma unroll
    for (int i = 0; i < 4; i++)
#pragma unroll
        for (int j = 0; j < 4; j++)
#pragma unroll
            for (int r = 0; r < 4; r++) acc[i][j][r] = 0.f;

    const int KT = K / 16;

    // prefetch tile 0
    float4 pa0 = *(const float4*)Ag0;
    float4 pa1 = *(const float4*)Ag1;
    float4 pb0 = *(const float4*)Bg0;
    float4 pb1 = *(const float4*)Bg1;

    // store tile 0 (tf32-rounded) into stage 0
    {
        float4 t;
        t.x = to_tf32(pa0.x); t.y = to_tf32(pa0.y); t.z = to_tf32(pa0.z); t.w = to_tf32(pa0.w);
        *(float4*)&Abuf[0][r0 * ASTR + c4] = t;
        t.x = to_tf32(pa1.x); t.y = to_tf32(pa1.y); t.z = to_tf32(pa1.z); t.w = to_tf32(pa1.w);
        *(float4*)&Abuf[0][(r0 + 64) * ASTR + c4] = t;
        t.x = to_tf32(pb0.x); t.y = to_tf32(pb0.y); t.z = to_tf32(pb0.z); t.w = to_tf32(pb0.w);
        *(float4*)&Bbuf[0][r0 * ASTR + c4] = t;
        t.x = to_tf32(pb1.x); t.y = to_tf32(pb1.y); t.z = to_tf32(pb1.z); t.w = to_tf32(pb1.w);
        *(float4*)&Bbuf[0][(r0 + 64) * ASTR + c4] = t;
    }
    __syncthreads();

    for (int kt = 0; kt < KT; kt++) {
        const int buf = kt & 1;
        const bool more = (kt + 1 < KT);

        // issue next tile's global loads early
        if (more) {
            const int ko = (kt + 1) * 16;
            pa0 = *(const float4*)(Ag0 + ko);
            pa1 = *(const float4*)(Ag1 + ko);
            pb0 = *(const float4*)(Bg0 + ko);
            pb1 = *(const float4*)(Bg1 + ko);
        }

        // compute 2 k8-steps from current buffer
        const float* Asb = Abuf[buf];
        const float* Bsb = Bbuf[buf];
#pragma unroll
        for (int s = 0; s < 2; s++) {
            float a[4][4];
#pragma unroll
            for (int mf = 0; mf < 4; mf++) {
                const int row = wm * 64 + mf * 16 + grp;
                const float2 lo = *(const float2*)&Asb[row * ASTR + s * 8 + 2 * qid];
                const float2 hi = *(const float2*)&Asb[(row + 8) * ASTR + s * 8 + 2 * qid];
                a[mf][0] = lo.x; a[mf][1] = hi.x; a[mf][2] = lo.y; a[mf][3] = hi.y;
            }
            float b[4][2];
#pragma unroll
            for (int nf = 0; nf < 4; nf++) {
                const int row = wn * 32 + nf * 8 + grp;
                const float2 bv = *(const float2*)&Bsb[row * ASTR + s * 8 + 2 * qid];
                b[nf][0] = bv.x; b[nf][1] = bv.y;
            }
#pragma unroll
            for (int mf = 0; mf < 4; mf++)
#pragma unroll
                for (int nf = 0; nf < 4; nf++)
                    mma_tf32(acc[mf][nf], a[mf], b[nf]);
        }

        // stage next tile into the other buffer
        if (more) {
            float* Ad = Abuf[buf ^ 1];
            float* Bd = Bbuf[buf ^ 1];
            float4 t;
            t.x = to_tf32(pa0.x); t.y = to_tf32(pa0.y); t.z = to_tf32(pa0.z); t.w = to_tf32(pa0.w);
            *(float4*)&Ad[r0 * ASTR + c4] = t;
            t.x = to_tf32(pa1.x); t.y = to_tf32(pa1.y); t.z = to_tf32(pa1.z); t.w = to_tf32(pa1.w);
            *(float4*)&Ad[(r0 + 64) * ASTR + c4] = t;
            t.x = to_tf32(pb0.x); t.y = to_tf32(pb0.y); t.z = to_tf32(pb0.z); t.w = to_tf32(pb0.w);
            *(float4*)&Bd[r0 * ASTR + c4] = t;
            t.x = to_tf32(pb1.x); t.y = to_tf32(pb1.y); t.z = to_tf32(pb1.z); t.w = to_tf32(pb1.w);
            *(float4*)&Bd[(r0 + 64) * ASTR + c4] = t;
            __syncthreads();
        }
    }

    // Epilogue: bias (+ReLU), float2 stores
#pragma unroll
    for (int mf = 0; mf < 4; mf++) {
#pragma unroll
        for (int nf = 0; nf < 4; nf++) {
            const int m0 = bm + wm * 64 + mf * 16 + grp;
            const int n0 = bn + wn * 32 + nf * 8 + 2 * qid;
            const float bx = bias[n0], by = bias[n0 + 1];
            float2 v0, v1;
            v0.x = acc[mf][nf][0] + bx; v0.y = acc[mf][nf][1] + by;
            v1.x = acc[mf][nf][2] + bx; v1.y = acc[mf][nf][3] + by;
            if (RELU) {
                v0.x = fmaxf(v0.x, 0.f); v0.y = fmaxf(v0.y, 0.f);
                v1.x = fmaxf(v1.x, 0.f); v1.y = fmaxf(v1.y, 0.f);
            }
            *(float2*)&C[(size_t)m0 * N + n0]       = v0;
            *(float2*)&C[(size_t)(m0 + 8) * N + n0] = v1;
        }
    }
}

// ---------------------------------------------------------------------------
// Flash attention (fp32, online softmax) — unchanged from R1.
// ---------------------------------------------------------------------------
#define AST 68
#define ATTN_SMEM_BYTES (4 * 64 * AST * 4 + 3 * 64 * 4)

__global__ __launch_bounds__(256)
void attn_kernel(const float* __restrict__ Q, const float* __restrict__ K,
                 const float* __restrict__ V, const int* __restrict__ mask,
                 float* __restrict__ O)
{
    extern __shared__ float sm[];
    float* Qs   = sm;
    float* Ks   = Qs + 64 * AST;
    float* Vt   = Ks + 64 * AST;
    float* Ps   = Vt + 64 * AST;
    float* mrow = Ps + 64 * AST;
    float* lrow = mrow + 64;
    float* arow = lrow + 64;

    const int tid = threadIdx.x;
    const int qt  = blockIdx.x;
    const int bh  = blockIdx.y;
    const int b   = bh >> 4;
    const int h   = bh & 15;
    const int q0  = qt * 64;
    const int tx  = tid & 15;
    const int ty  = tid >> 4;

    const size_t headoff = (size_t)b * S_ * D_ + (size_t)h * HD_;
    const float* Qb = Q + headoff;
    const float* Kb = K + headoff;
    const float* Vb = V + headoff;

    {
        const int r  = tid >> 2;
        const int c0 = (tid & 3) * 16;
        const float* src = Qb + (size_t)(q0 + r) * D_ + c0;
#pragma unroll
        for (int i = 0; i < 4; i++)
            *(float4*)&Qs[r * AST + c0 + i * 4] = *(const float4*)(src + i * 4);
    }
    if (tid < 64) { mrow[tid] = -1e30f; lrow[tid] = 0.f; }

    float acc[4][4];
#pragma unroll
    for (int i = 0; i < 4; i++)
#pragma unroll
        for (int j = 0; j < 4; j++) acc[i][j] = 0.f;

    for (int kt = 0; kt < S_ / 64; kt++) {
        const int k0 = kt * 64;
        __syncthreads();
        {
            const int r  = tid >> 2;
            const int c0 = (tid & 3) * 16;
            const float* ksrc = Kb + (size_t)(k0 + r) * D_ + c0;
            const float* vsrc = Vb + (size_t)(k0 + r) * D_ + c0;
#pragma unroll
            for (int i = 0; i < 4; i++) {
                *(float4*)&Ks[r * AST + c0 + i * 4] = *(const float4*)(ksrc + i * 4);
                const float4 vv = *(const float4*)(vsrc + i * 4);
                Vt[(c0 + i * 4 + 0) * AST + r] = vv.x;
                Vt[(c0 + i * 4 + 1) * AST + r] = vv.y;
                Vt[(c0 + i * 4 + 2) * AST + r] = vv.z;
                Vt[(c0 + i * 4 + 3) * AST + r] = vv.w;
            }
        }
        __syncthreads();

        float s[4][4];
#pragma unroll
        for (int i = 0; i < 4; i++)
#pragma unroll
            for (int j = 0; j < 4; j++) s[i][j] = 0.f;

#pragma unroll
        for (int d4 = 0; d4 < 16; d4++) {
            float4 q4[4], k4[4];
#pragma unroll
            for (int i = 0; i < 4; i++)
                q4[i] = *(const float4*)&Qs[(ty * 4 + i) * AST + d4 * 4];
#pragma unroll
            for (int j = 0; j < 4; j++)
                k4[j] = *(const float4*)&Ks[(tx + 16 * j) * AST + d4 * 4];
#pragma unroll
            for (int i = 0; i < 4; i++)
#pragma unroll
                for (int j = 0; j < 4; j++)
                    s[i][j] += q4[i].x * k4[j].x + q4[i].y * k4[j].y +
                               q4[i].z * k4[j].z + q4[i].w * k4[j].w;
        }

        const int* mb = mask + ((size_t)b * S_ + q0) * S_ + k0;
#pragma unroll
        for (int i = 0; i < 4; i++)
#pragma unroll
            for (int j = 0; j < 4; j++) {
                float v = s[i][j] * 0.125f;
                if (mb[(size_t)(ty * 4 + i) * S_ + tx + 16 * j] == 0) v = -1e8f;
                Ps[(ty * 4 + i) * AST + tx + 16 * j] = v;
            }
        __syncthreads();

        if (tid < 64) {
            const int r = tid;
            const float mprev = mrow[r];
            float mx = mprev;
#pragma unroll 8
            for (int c = 0; c < 64; c++) mx = fmaxf(mx, Ps[r * AST + c]);
            const float alpha = __expf(mprev - mx);
            float sum = 0.f;
#pragma unroll 8
            for (int c = 0; c < 64; c++) {
                const float e = __expf(Ps[r * AST + c] - mx);
                Ps[r * AST + c] = e;
                sum += e;
            }
            lrow[r] = lrow[r] * alpha + sum;
            mrow[r] = mx;
            arow[r] = alpha;
        }
        __syncthreads();

        float al[4];
#pragma unroll
        for (int i = 0; i < 4; i++) al[i] = arow[ty * 4 + i];
#pragma unroll
        for (int i = 0; i < 4; i++)
#pragma unroll
            for (int j = 0; j < 4; j++) acc[i][j] *= al[i];

#pragma unroll
        for (int k4 = 0; k4 < 16; k4++) {
            float4 p4[4], v4[4];
#pragma unroll
            for (int i = 0; i < 4; i++)
                p4[i] = *(const float4*)&Ps[(ty * 4 + i) * AST + k4 * 4];
#pragma unroll
            for (int j = 0; j < 4; j++)
                v4[j] = *(const float4*)&Vt[(tx + 16 * j) * AST + k4 * 4];
#pragma unroll
            for (int i = 0; i < 4; i++)
#pragma unroll
                for (int j = 0; j < 4; j++)
                    acc[i][j] += p4[i].x * v4[j].x + p4[i].y * v4[j].y +
                                 p4[i].z * v4[j].z + p4[i].w * v4[j].w;
        }
    }

#pragma unroll
    for (int i = 0; i < 4; i++) {
        const int r = ty * 4 + i;
        const float inv = 1.0f / lrow[r];
        const size_t rowoff = (size_t)(b * S_ + q0 + r) * D_ + (size_t)h * HD_;
#pragma unroll
        for (int j = 0; j < 4; j++)
            O[rowoff + tx + 16 * j] = acc[i][j] * inv;
    }
}

// ---------------------------------------------------------------------------
// Launch
// Inputs (metadata order): x, Wq, bq, Wk, bk, Wv, bv, W1, b1, W2, b2, mask
// ---------------------------------------------------------------------------
extern "C" void kernel_launch(void* const* d_in, const int* in_sizes, int n_in,
                              void* d_out, int out_size)
{
    const float* x    = (const float*)d_in[0];
    const float* Wq   = (const float*)d_in[1];
    const float* bq   = (const float*)d_in[2];
    const float* Wk   = (const float*)d_in[3];
    const float* bk   = (const float*)d_in[4];
    const float* Wv   = (const float*)d_in[5];
    const float* bv   = (const float*)d_in[6];
    const float* W1   = (const float*)d_in[7];
    const float* b1   = (const float*)d_in[8];
    const float* W2   = (const float*)d_in[9];
    const float* b2   = (const float*)d_in[10];
    const int*   mask = (const int*)d_in[11];
    float*       out  = (float*)d_out;

    float *Qp, *Kp, *Vp, *Cp, *Hp;
    cudaGetSymbolAddress((void**)&Qp, g_Q);
    cudaGetSymbolAddress((void**)&Kp, g_K);
    cudaGetSymbolAddress((void**)&Vp, g_V);
    cudaGetSymbolAddress((void**)&Cp, g_C);
    cudaGetSymbolAddress((void**)&Hp, g_Hid);

    cudaFuncSetAttribute(attn_kernel,
                         cudaFuncAttributeMaxDynamicSharedMemorySize,
                         ATTN_SMEM_BYTES);
    cudaFuncSetAttribute(gemm_tc<false>,
                         cudaFuncAttributeMaxDynamicSharedMemorySize,
                         GEMM_SMEM_BYTES);
    cudaFuncSetAttribute(gemm_tc<true>,
                         cudaFuncAttributeMaxDynamicSharedMemorySize,
                         GEMM_SMEM_BYTES);

    const dim3 blk(256);

    // QKV projections
    gemm_tc<false><<<dim3(D_ / 128, M_ / 128), blk, GEMM_SMEM_BYTES>>>(x, Wq, bq, Qp, M_, D_, D_);
    gemm_tc<false><<<dim3(D_ / 128, M_ / 128), blk, GEMM_SMEM_BYTES>>>(x, Wk, bk, Kp, M_, D_, D_);
    gemm_tc<false><<<dim3(D_ / 128, M_ / 128), blk, GEMM_SMEM_BYTES>>>(x, Wv, bv, Vp, M_, D_, D_);

    // Attention
    attn_kernel<<<dim3(S_ / 64, B_ * H_), blk, ATTN_SMEM_BYTES>>>(Qp, Kp, Vp, mask, Cp);

    // MLP
    gemm_tc<true ><<<dim3(2 * D_ / 128, M_ / 128), blk, GEMM_SMEM_BYTES>>>(Cp, W1, b1, Hp, M_, 2 * D_, D_);
    gemm_tc<false><<<dim3(D_ / 128, M_ / 128), blk, GEMM_SMEM_BYTES>>>(Hp, W2, b2, out, M_, D_, 2 * D_);
}

// round 3
// speedup vs baseline: 1.7725x; 1.2266x over previous
#include <cuda_runtime.h>
#include <stdint.h>

#define B_  4
#define S_  1024
#define D_  1024
#define H_  16
#define HD_ 64
#define M_  (B_ * S_)     // 4096

// ---------------------------------------------------------------------------
// Scratch (device globals)
// ---------------------------------------------------------------------------
__device__ __align__(16) float g_X   [(size_t)M_ * D_];        // tf32-rounded x
__device__ __align__(16) float g_Wqkv[(size_t)3 * D_ * D_];    // rounded, concat
__device__ __align__(16) float g_bqkv[3 * D_];
__device__ __align__(16) float g_W1r [(size_t)2 * D_ * D_];
__device__ __align__(16) float g_W2r [(size_t)2 * D_ * D_];
__device__ __align__(16) float g_QKV [(size_t)M_ * 3 * D_];    // fp32 Q|K|V
__device__ __align__(16) float g_C   [(size_t)M_ * D_];        // ctx (tf32-rounded)
__device__ __align__(16) float g_Hid [(size_t)M_ * 2 * D_];    // hidden (tf32-rounded)

// ---------------------------------------------------------------------------
__device__ __forceinline__ float to_tf32(float x) {
    uint32_t u;
    asm("cvt.rna.tf32.f32 %0, %1;" : "=r"(u) : "f"(x));
    return __uint_as_float(u);
}

__device__ __forceinline__ void mma_tf32(float* c, const float* a, const float* b) {
    asm volatile(
        "mma.sync.aligned.m16n8k8.row.col.f32.tf32.tf32.f32 "
        "{%0,%1,%2,%3}, {%4,%5,%6,%7}, {%8,%9}, {%0,%1,%2,%3};\n"
        : "+f"(c[0]), "+f"(c[1]), "+f"(c[2]), "+f"(c[3])
        : "r"(__float_as_uint(a[0])), "r"(__float_as_uint(a[1])),
          "r"(__float_as_uint(a[2])), "r"(__float_as_uint(a[3])),
          "r"(__float_as_uint(b[0])), "r"(__float_as_uint(b[1])));
}

// ---------------------------------------------------------------------------
// Prep kernels
// ---------------------------------------------------------------------------
__global__ void round_copy4(const float* __restrict__ src, float* __restrict__ dst, int n4) {
    const int i = blockIdx.x * blockDim.x + threadIdx.x;
    if (i < n4) {
        float4 v = ((const float4*)src)[i];
        v.x = to_tf32(v.x); v.y = to_tf32(v.y);
        v.z = to_tf32(v.z); v.w = to_tf32(v.w);
        ((float4*)dst)[i] = v;
    }
}

__global__ void concat_bias(const float* __restrict__ a, const float* __restrict__ b,
                            const float* __restrict__ c, float* __restrict__ dst) {
    const int i = blockIdx.x * blockDim.x + threadIdx.x;
    if (i < 3 * D_)
        dst[i] = (i < D_) ? a[i] : ((i < 2 * D_) ? b[i - D_] : c[i - 2 * D_]);
}

// ---------------------------------------------------------------------------
// Tensor-core GEMM (tf32, inputs pre-rounded):
//   C[m,n] = sum_k A[m,k]*B[n,k] + bias[n]   ("NT", row-major)
// 128x128 tile, K-tile 16, 256 threads, warp tile 64x32, double-buffered.
// k-permutation on smem storage makes each fragment one conflict-light LDS.64:
// both A and B use the same permutation, so the dot product is unchanged.
// Target 2 blocks/SM.
// ---------------------------------------------------------------------------
#define ASTR 24
#define STAGE_FLOATS (128 * ASTR)
#define GEMM_SMEM_BYTES (4 * STAGE_FLOATS * 4)   // 48 KB

template <bool RELU, bool ROUND_OUT>
__global__ __launch_bounds__(256, 2)
void gemm_tc(const float* __restrict__ A, const float* __restrict__ Bm,
             const float* __restrict__ bias, float* __restrict__ C,
             int M, int N, int K)
{
    extern __shared__ float sm[];
    float* Abuf[2] = { sm, sm + STAGE_FLOATS };
    float* Bbuf[2] = { sm + 2 * STAGE_FLOATS, sm + 3 * STAGE_FLOATS };

    const int tid  = threadIdx.x;
    const int lane = tid & 31;
    const int wid  = tid >> 5;
    const int wm   = wid >> 2;
    const int wn   = wid & 3;
    const int grp  = lane >> 2;
    const int qid  = lane & 3;

    const int bm = blockIdx.y * 128;
    const int bn = blockIdx.x * 128;

    const int r0 = tid >> 2;
    const int c4 = (tid & 3) * 4;
    const float* Ag0 = A  + (size_t)(bm + r0)      * K + c4;
    const float* Ag1 = A  + (size_t)(bm + r0 + 64) * K + c4;
    const float* Bg0 = Bm + (size_t)(bn + r0)      * K + c4;
    const float* Bg1 = Bm + (size_t)(bn + r0 + 64) * K + c4;

    float acc[4][4][4];
#pragma unroll
    for (int i = 0; i < 4; i++)
#pragma unroll
        for (int j = 0; j < 4; j++)
#pragma unroll
            for (int r = 0; r < 4; r++) acc[i][j][r] = 0.f;

    const int KT = K / 16;

    float4 pa0 = *(const float4*)Ag0;
    float4 pa1 = *(const float4*)Ag1;
    float4 pb0 = *(const float4*)Bg0;
    float4 pb1 = *(const float4*)Bg1;

    *(float4*)&Abuf[0][r0 * ASTR + c4]        = pa0;
    *(float4*)&Abuf[0][(r0 + 64) * ASTR + c4] = pa1;
    *(float4*)&Bbuf[0][r0 * ASTR + c4]        = pb0;
    *(float4*)&Bbuf[0][(r0 + 64) * ASTR + c4] = pb1;
    __syncthreads();

    for (int kt = 0; kt < KT; kt++) {
        const int buf = kt & 1;
        const bool more = (kt + 1 < KT);

        if (more) {
            const int ko = (kt + 1) * 16;
            pa0 = *(const float4*)(Ag0 + ko);
            pa1 = *(const float4*)(Ag1 + ko);
            pb0 = *(const float4*)(Bg0 + ko);
            pb1 = *(const float4*)(Bg1 + ko);
        }

        const float* Asb = Abuf[buf];
        const float* Bsb = Bbuf[buf];
#pragma unroll
        for (int s = 0; s < 2; s++) {
            float a[4][4];
#pragma unroll
            for (int mf = 0; mf < 4; mf++) {
                const int row = wm * 64 + mf * 16 + grp;
                const float2 lo = *(const float2*)&Asb[row * ASTR + s * 8 + 2 * qid];
                const float2 hi = *(const float2*)&Asb[(row + 8) * ASTR + s * 8 + 2 * qid];
                a[mf][0] = lo.x; a[mf][1] = hi.x; a[mf][2] = lo.y; a[mf][3] = hi.y;
            }
            float b[4][2];
#pragma unroll
            for (int nf = 0; nf < 4; nf++) {
                const int row = wn * 32 + nf * 8 + grp;
                const float2 bv = *(const float2*)&Bsb[row * ASTR + s * 8 + 2 * qid];
                b[nf][0] = bv.x; b[nf][1] = bv.y;
            }
#pragma unroll
            for (int mf = 0; mf < 4; mf++)
#pragma unroll
                for (int nf = 0; nf < 4; nf++)
                    mma_tf32(acc[mf][nf], a[mf], b[nf]);
        }

        if (more) {
            float* Ad = Abuf[buf ^ 1];
            float* Bd = Bbuf[buf ^ 1];
            *(float4*)&Ad[r0 * ASTR + c4]        = pa0;
            *(float4*)&Ad[(r0 + 64) * ASTR + c4] = pa1;
            *(float4*)&Bd[r0 * ASTR + c4]        = pb0;
            *(float4*)&Bd[(r0 + 64) * ASTR + c4] = pb1;
            __syncthreads();
        }
    }

#pragma unroll
    for (int mf = 0; mf < 4; mf++) {
#pragma unroll
        for (int nf = 0; nf < 4; nf++) {
            const int m0 = bm + wm * 64 + mf * 16 + grp;
            const int n0 = bn + wn * 32 + nf * 8 + 2 * qid;
            const float bx = bias[n0], by = bias[n0 + 1];
            float2 v0, v1;
            v0.x = acc[mf][nf][0] + bx; v0.y = acc[mf][nf][1] + by;
            v1.x = acc[mf][nf][2] + bx; v1.y = acc[mf][nf][3] + by;
            if (RELU) {
                v0.x = fmaxf(v0.x, 0.f); v0.y = fmaxf(v0.y, 0.f);
                v1.x = fmaxf(v1.x, 0.f); v1.y = fmaxf(v1.y, 0.f);
            }
            if (ROUND_OUT) {
                v0.x = to_tf32(v0.x); v0.y = to_tf32(v0.y);
                v1.x = to_tf32(v1.x); v1.y = to_tf32(v1.y);
            }
            *(float2*)&C[(size_t)m0 * N + n0]       = v0;
            *(float2*)&C[(size_t)(m0 + 8) * N + n0] = v1;
        }
    }
}

// ---------------------------------------------------------------------------
// Flash attention (fp32, register-resident online softmax).
// QKV packed: row stride 3*D, Q at h*64, K at D+h*64, V at 2D+h*64.
// Output ctx written tf32-rounded (consumed by tf32 GEMM anyway).
// ---------------------------------------------------------------------------
#define AST 68
#define ATTN_SMEM_BYTES (4 * 64 * AST * 4)

__global__ __launch_bounds__(256)
void attn_kernel(const float* __restrict__ QKV, const int* __restrict__ mask,
                 float* __restrict__ O)
{
    extern __shared__ float smf[];
    float* Qs = smf;
    float* Ks = Qs + 64 * AST;
    float* Vt = Ks + 64 * AST;
    float* Ps = Vt + 64 * AST;

    const int tid = threadIdx.x;
    const int qt  = blockIdx.x;
    const int bh  = blockIdx.y;
    const int b   = bh >> 4;
    const int h   = bh & 15;
    const int q0  = qt * 64;
    const int tx  = tid & 15;
    const int ty  = tid >> 4;

    const int LDQ = 3 * D_;
    const float* Qb = QKV + (size_t)b * S_ * LDQ + (size_t)h * HD_;
    const float* Kb = Qb + D_;
    const float* Vb = Qb + 2 * D_;

    {
        const int r  = tid >> 2;
        const int c0 = (tid & 3) * 16;
        const float* src = Qb + (size_t)(q0 + r) * LDQ + c0;
#pragma unroll
        for (int i = 0; i < 4; i++)
            *(float4*)&Qs[r * AST + c0 + i * 4] = *(const float4*)(src + i * 4);
    }

    float mi[4], li[4];
#pragma unroll
    for (int i = 0; i < 4; i++) { mi[i] = -1e30f; li[i] = 0.f; }

    float acc[4][4];
#pragma unroll
    for (int i = 0; i < 4; i++)
#pragma unroll
        for (int j = 0; j < 4; j++) acc[i][j] = 0.f;

    for (int kt = 0; kt < S_ / 64; kt++) {
        const int k0 = kt * 64;
        __syncthreads();   // prior PV done / Q visible
        {
            const int r  = tid >> 2;
            const int c0 = (tid & 3) * 16;
            const float* ksrc = Kb + (size_t)(k0 + r) * LDQ + c0;
            const float* vsrc = Vb + (size_t)(k0 + r) * LDQ + c0;
#pragma unroll
            for (int i = 0; i < 4; i++) {
                *(float4*)&Ks[r * AST + c0 + i * 4] = *(const float4*)(ksrc + i * 4);
                const float4 vv = *(const float4*)(vsrc + i * 4);
                Vt[(c0 + i * 4 + 0) * AST + r] = vv.x;
                Vt[(c0 + i * 4 + 1) * AST + r] = vv.y;
                Vt[(c0 + i * 4 + 2) * AST + r] = vv.z;
                Vt[(c0 + i * 4 + 3) * AST + r] = vv.w;
            }
        }
        __syncthreads();

        // Scores
        float s[4][4];
#pragma unroll
        for (int i = 0; i < 4; i++)
#pragma unroll
            for (int j = 0; j < 4; j++) s[i][j] = 0.f;

#pragma unroll
        for (int d4 = 0; d4 < 16; d4++) {
            float4 q4[4], k4[4];
#pragma unroll
            for (int i = 0; i < 4; i++)
                q4[i] = *(const float4*)&Qs[(ty * 4 + i) * AST + d4 * 4];
#pragma unroll
            for (int j = 0; j < 4; j++)
                k4[j] = *(const float4*)&Ks[(tx + 16 * j) * AST + d4 * 4];
#pragma unroll
            for (int i = 0; i < 4; i++)
#pragma unroll
                for (int j = 0; j < 4; j++)
                    s[i][j] += q4[i].x * k4[j].x + q4[i].y * k4[j].y +
                               q4[i].z * k4[j].z + q4[i].w * k4[j].w;
        }

        // Scale + mask in regs
        const int* mb = mask + ((size_t)b * S_ + q0) * S_ + k0;
#pragma unroll
        for (int i = 0; i < 4; i++)
#pragma unroll
            for (int j = 0; j < 4; j++) {
                float v = s[i][j] * 0.125f;
                if (mb[(size_t)(ty * 4 + i) * S_ + tx + 16 * j] == 0) v = -1e8f;
                s[i][j] = v;
            }

        // Register online softmax; stats replicated across the 16 tx-threads
        // (xor masks 1,2,4,8 stay inside each 16-lane group of the warp).
#pragma unroll
        for (int i = 0; i < 4; i++) {
            float r = fmaxf(fmaxf(s[i][0], s[i][1]), fmaxf(s[i][2], s[i][3]));
            r = fmaxf(r, __shfl_xor_sync(0xffffffffu, r, 1));
            r = fmaxf(r, __shfl_xor_sync(0xffffffffu, r, 2));
            r = fmaxf(r, __shfl_xor_sync(0xffffffffu, r, 4));
            r = fmaxf(r, __shfl_xor_sync(0xffffffffu, r, 8));
            const float mnew  = fmaxf(mi[i], r);
            const float alpha = __expf(mi[i] - mnew);
            float sum = 0.f;
#pragma unroll
            for (int j = 0; j < 4; j++) {
                const float e = __expf(s[i][j] - mnew);
                Ps[(ty * 4 + i) * AST + tx + 16 * j] = e;
                sum += e;
            }
            sum += __shfl_xor_sync(0xffffffffu, sum, 1);
            sum += __shfl_xor_sync(0xffffffffu, sum, 2);
            sum += __shfl_xor_sync(0xffffffffu, sum, 4);
            sum += __shfl_xor_sync(0xffffffffu, sum, 8);
            li[i] = li[i] * alpha + sum;
            mi[i] = mnew;
#pragma unroll
            for (int j = 0; j < 4; j++) acc[i][j] *= alpha;
        }
        __syncthreads();   // Ps visible

        // PV
#pragma unroll
        for (int k4 = 0; k4 < 16; k4++) {
            float4 p4[4], v4[4];
#pragma unroll
            for (int i = 0; i < 4; i++)
                p4[i] = *(const float4*)&Ps[(ty * 4 + i) * AST + k4 * 4];
#pragma unroll
            for (int j = 0; j < 4; j++)
                v4[j] = *(const float4*)&Vt[(tx + 16 * j) * AST + k4 * 4];
#pragma unroll
            for (int i = 0; i < 4; i++)
#pragma unroll
                for (int j = 0; j < 4; j++)
                    acc[i][j] += p4[i].x * v4[j].x + p4[i].y * v4[j].y +
                                 p4[i].z * v4[j].z + p4[i].w * v4[j].w;
        }
    }

    // Finalize (tf32-rounded ctx)
#pragma unroll
    for (int i = 0; i < 4; i++) {
        const float inv = 1.0f / li[i];
        const size_t rowoff = (size_t)(b * S_ + q0 + ty * 4 + i) * D_ + (size_t)h * HD_;
#pragma unroll
        for (int j = 0; j < 4; j++)
            O[rowoff + tx + 16 * j] = to_tf32(acc[i][j] * inv);
    }
}

// ---------------------------------------------------------------------------
// Launch.  Inputs: x, Wq, bq, Wk, bk, Wv, bv, W1, b1, W2, b2, mask
// ---------------------------------------------------------------------------
extern "C" void kernel_launch(void* const* d_in, const int* in_sizes, int n_in,
                              void* d_out, int out_size)
{
    const float* x    = (const float*)d_in[0];
    const float* Wq   = (const float*)d_in[1];
    const float* bq   = (const float*)d_in[2];
    const float* Wk   = (const float*)d_in[3];
    const float* bk   = (const float*)d_in[4];
    const float* Wv   = (const float*)d_in[5];
    const float* bv   = (const float*)d_in[6];
    const float* W1   = (const float*)d_in[7];
    const float* b1   = (const float*)d_in[8];
    const float* W2   = (const float*)d_in[9];
    const float* b2   = (const float*)d_in[10];
    const int*   mask = (const int*)d_in[11];
    float*       out  = (float*)d_out;

    float *Xp, *Wqkvp, *bqkvp, *W1p, *W2p, *QKVp, *Cp, *Hp;
    cudaGetSymbolAddress((void**)&Xp,    g_X);
    cudaGetSymbolAddress((void**)&Wqkvp, g_Wqkv);
    cudaGetSymbolAddress((void**)&bqkvp, g_bqkv);
    cudaGetSymbolAddress((void**)&W1p,   g_W1r);
    cudaGetSymbolAddress((void**)&W2p,   g_W2r);
    cudaGetSymbolAddress((void**)&QKVp,  g_QKV);
    cudaGetSymbolAddress((void**)&Cp,    g_C);
    cudaGetSymbolAddress((void**)&Hp,    g_Hid);

    cudaFuncSetAttribute(attn_kernel,
                         cudaFuncAttributeMaxDynamicSharedMemorySize, ATTN_SMEM_BYTES);
    cudaFuncSetAttribute((const void*)gemm_tc<false,false>,
                         cudaFuncAttributeMaxDynamicSharedMemorySize, GEMM_SMEM_BYTES);
    cudaFuncSetAttribute((const void*)gemm_tc<true,true>,
                         cudaFuncAttributeMaxDynamicSharedMemorySize, GEMM_SMEM_BYTES);

    const dim3 blk(256);

    // ---- prep: round inputs to tf32 once ----
    const int T = 256;
    round_copy4<<<(M_ * D_ / 4 + T - 1) / T, T>>>(x,  Xp,              M_ * D_ / 4);
    round_copy4<<<(D_ * D_ / 4 + T - 1) / T, T>>>(Wq, Wqkvp,           D_ * D_ / 4);
    round_copy4<<<(D_ * D_ / 4 + T - 1) / T, T>>>(Wk, Wqkvp + D_ * D_, D_ * D_ / 4);
    round_copy4<<<(D_ * D_ / 4 + T - 1) / T, T>>>(Wv, Wqkvp + 2 * D_ * D_, D_ * D_ / 4);
    round_copy4<<<(2 * D_ * D_ / 4 + T - 1) / T, T>>>(W1, W1p, 2 * D_ * D_ / 4);
    round_copy4<<<(2 * D_ * D_ / 4 + T - 1) / T, T>>>(W2, W2p, 2 * D_ * D_ / 4);
    concat_bias<<<(3 * D_ + T - 1) / T, T>>>(bq, bk, bv, bqkvp);

    // ---- fused QKV projection: [4096,3072] ----
    gemm_tc<false,false><<<dim3(3 * D_ / 128, M_ / 128), blk, GEMM_SMEM_BYTES>>>(
        Xp, Wqkvp, bqkvp, QKVp, M_, 3 * D_, D_);

    // ---- attention ----
    attn_kernel<<<dim3(S_ / 64, B_ * H_), blk, ATTN_SMEM_BYTES>>>(QKVp, mask, Cp);

    // ---- MLP ----
    gemm_tc<true,true ><<<dim3(2 * D_ / 128, M_ / 128), blk, GEMM_SMEM_BYTES>>>(
        Cp, W1p, b1, Hp, M_, 2 * D_, D_);
    gemm_tc<false,false><<<dim3(D_ / 128, M_ / 128), blk, GEMM_SMEM_BYTES>>>(
        Hp, W2p, b2, out, M_, D_, 2 * D_);
}

// round 4
// speedup vs baseline: 2.3702x; 1.3372x over previous
#include <cuda_runtime.h>
#include <stdint.h>

#define B_  4
#define S_  1024
#define D_  1024
#define H_  16
#define HD_ 64
#define M_  (B_ * S_)     // 4096

// ---------------------------------------------------------------------------
// Scratch (device globals)
// ---------------------------------------------------------------------------
__device__ __align__(16) float g_X   [(size_t)M_ * D_];
__device__ __align__(16) float g_Wqkv[(size_t)3 * D_ * D_];
__device__ __align__(16) float g_bqkv[3 * D_];
__device__ __align__(16) float g_W1r [(size_t)2 * D_ * D_];
__device__ __align__(16) float g_W2r [(size_t)2 * D_ * D_];
__device__ __align__(16) float g_QKV [(size_t)M_ * 3 * D_];
__device__ __align__(16) float g_C   [(size_t)M_ * D_];
__device__ __align__(16) float g_Hid [(size_t)M_ * 2 * D_];

// ---------------------------------------------------------------------------
__device__ __forceinline__ float to_tf32(float x) {
    uint32_t u;
    asm("cvt.rna.tf32.f32 %0, %1;" : "=r"(u) : "f"(x));
    return __uint_as_float(u);
}

__device__ __forceinline__ void mma_tf32(float* c, const float* a, const float* b) {
    asm volatile(
        "mma.sync.aligned.m16n8k8.row.col.f32.tf32.tf32.f32 "
        "{%0,%1,%2,%3}, {%4,%5,%6,%7}, {%8,%9}, {%0,%1,%2,%3};\n"
        : "+f"(c[0]), "+f"(c[1]), "+f"(c[2]), "+f"(c[3])
        : "r"(__float_as_uint(a[0])), "r"(__float_as_uint(a[1])),
          "r"(__float_as_uint(a[2])), "r"(__float_as_uint(a[3])),
          "r"(__float_as_uint(b[0])), "r"(__float_as_uint(b[1])));
}

// ---------------------------------------------------------------------------
// Prep kernels
// ---------------------------------------------------------------------------
__global__ void round_copy4(const float* __restrict__ src, float* __restrict__ dst, int n4) {
    const int i = blockIdx.x * blockDim.x + threadIdx.x;
    if (i < n4) {
        float4 v = ((const float4*)src)[i];
        v.x = to_tf32(v.x); v.y = to_tf32(v.y);
        v.z = to_tf32(v.z); v.w = to_tf32(v.w);
        ((float4*)dst)[i] = v;
    }
}

__global__ void concat_bias(const float* __restrict__ a, const float* __restrict__ b,
                            const float* __restrict__ c, float* __restrict__ dst) {
    const int i = blockIdx.x * blockDim.x + threadIdx.x;
    if (i < 3 * D_)
        dst[i] = (i < D_) ? a[i] : ((i < 2 * D_) ? b[i - D_] : c[i - 2 * D_]);
}

// ---------------------------------------------------------------------------
// Tensor-core GEMM (tf32, inputs pre-rounded) — unchanged from R3.
// ---------------------------------------------------------------------------
#define ASTR 24
#define STAGE_FLOATS (128 * ASTR)
#define GEMM_SMEM_BYTES (4 * STAGE_FLOATS * 4)   // 48 KB

template <bool RELU, bool ROUND_OUT>
__global__ __launch_bounds__(256, 2)
void gemm_tc(const float* __restrict__ A, const float* __restrict__ Bm,
             const float* __restrict__ bias, float* __restrict__ C,
             int M, int N, int K)
{
    extern __shared__ float sm[];
    float* Abuf[2] = { sm, sm + STAGE_FLOATS };
    float* Bbuf[2] = { sm + 2 * STAGE_FLOATS, sm + 3 * STAGE_FLOATS };

    const int tid  = threadIdx.x;
    const int lane = tid & 31;
    const int wid  = tid >> 5;
    const int wm   = wid >> 2;
    const int wn   = wid & 3;
    const int grp  = lane >> 2;
    const int qid  = lane & 3;

    const int bm = blockIdx.y * 128;
    const int bn = blockIdx.x * 128;

    const int r0 = tid >> 2;
    const int c4 = (tid & 3) * 4;
    const float* Ag0 = A  + (size_t)(bm + r0)      * K + c4;
    const float* Ag1 = A  + (size_t)(bm + r0 + 64) * K + c4;
    const float* Bg0 = Bm + (size_t)(bn + r0)      * K + c4;
    const float* Bg1 = Bm + (size_t)(bn + r0 + 64) * K + c4;

    float acc[4][4][4];
#pragma unroll
    for (int i = 0; i < 4; i++)
#pragma unroll
        for (int j = 0; j < 4; j++)
#pragma unroll
            for (int r = 0; r < 4; r++) acc[i][j][r] = 0.f;

    const int KT = K / 16;

    float4 pa0 = *(const float4*)Ag0;
    float4 pa1 = *(const float4*)Ag1;
    float4 pb0 = *(const float4*)Bg0;
    float4 pb1 = *(const float4*)Bg1;

    *(float4*)&Abuf[0][r0 * ASTR + c4]        = pa0;
    *(float4*)&Abuf[0][(r0 + 64) * ASTR + c4] = pa1;
    *(float4*)&Bbuf[0][r0 * ASTR + c4]        = pb0;
    *(float4*)&Bbuf[0][(r0 + 64) * ASTR + c4] = pb1;
    __syncthreads();

    for (int kt = 0; kt < KT; kt++) {
        const int buf = kt & 1;
        const bool more = (kt + 1 < KT);

        if (more) {
            const int ko = (kt + 1) * 16;
            pa0 = *(const float4*)(Ag0 + ko);
            pa1 = *(const float4*)(Ag1 + ko);
            pb0 = *(const float4*)(Bg0 + ko);
            pb1 = *(const float4*)(Bg1 + ko);
        }

        const float* Asb = Abuf[buf];
        const float* Bsb = Bbuf[buf];
#pragma unroll
        for (int s = 0; s < 2; s++) {
            float a[4][4];
#pragma unroll
            for (int mf = 0; mf < 4; mf++) {
                const int row = wm * 64 + mf * 16 + grp;
                const float2 lo = *(const float2*)&Asb[row * ASTR + s * 8 + 2 * qid];
                const float2 hi = *(const float2*)&Asb[(row + 8) * ASTR + s * 8 + 2 * qid];
                a[mf][0] = lo.x; a[mf][1] = hi.x; a[mf][2] = lo.y; a[mf][3] = hi.y;
            }
            float b[4][2];
#pragma unroll
            for (int nf = 0; nf < 4; nf++) {
                const int row = wn * 32 + nf * 8 + grp;
                const float2 bv = *(const float2*)&Bsb[row * ASTR + s * 8 + 2 * qid];
                b[nf][0] = bv.x; b[nf][1] = bv.y;
            }
#pragma unroll
            for (int mf = 0; mf < 4; mf++)
#pragma unroll
                for (int nf = 0; nf < 4; nf++)
                    mma_tf32(acc[mf][nf], a[mf], b[nf]);
        }

        if (more) {
            float* Ad = Abuf[buf ^ 1];
            float* Bd = Bbuf[buf ^ 1];
            *(float4*)&Ad[r0 * ASTR + c4]        = pa0;
            *(float4*)&Ad[(r0 + 64) * ASTR + c4] = pa1;
            *(float4*)&Bd[r0 * ASTR + c4]        = pb0;
            *(float4*)&Bd[(r0 + 64) * ASTR + c4] = pb1;
            __syncthreads();
        }
    }

#pragma unroll
    for (int mf = 0; mf < 4; mf++) {
#pragma unroll
        for (int nf = 0; nf < 4; nf++) {
            const int m0 = bm + wm * 64 + mf * 16 + grp;
            const int n0 = bn + wn * 32 + nf * 8 + 2 * qid;
            const float bx = bias[n0], by = bias[n0 + 1];
            float2 v0, v1;
            v0.x = acc[mf][nf][0] + bx; v0.y = acc[mf][nf][1] + by;
            v1.x = acc[mf][nf][2] + bx; v1.y = acc[mf][nf][3] + by;
            if (RELU) {
                v0.x = fmaxf(v0.x, 0.f); v0.y = fmaxf(v0.y, 0.f);
                v1.x = fmaxf(v1.x, 0.f); v1.y = fmaxf(v1.y, 0.f);
            }
            if (ROUND_OUT) {
                v0.x = to_tf32(v0.x); v0.y = to_tf32(v0.y);
                v1.x = to_tf32(v1.x); v1.y = to_tf32(v1.y);
            }
            *(float2*)&C[(size_t)m0 * N + n0]       = v0;
            *(float2*)&C[(size_t)(m0 + 8) * N + n0] = v1;
        }
    }
}

// ---------------------------------------------------------------------------
// Tensor-core flash attention (tf32 mma, register-fragment softmax).
// q-tile 128, k-tile 64, 8 warps; warp w owns query rows w*16..w*16+15 fully.
// QK^T C-fragment == PV A-fragment under the shared k-relabeling, so P stays
// in registers (no smem stores, no extra syncs).
// QKV packed rows of 3*D: Q at h*64, K at D+h*64, V at 2D+h*64.
// ---------------------------------------------------------------------------
#define AST 68
#define QT_ 128
#define ATTN_SMEM_BYTES ((QT_ + 64 + 64) * AST * 4)   // 69,632 B

__global__ __launch_bounds__(256, 2)
void attn_tc(const float* __restrict__ QKV, const int* __restrict__ mask,
             float* __restrict__ O)
{
    extern __shared__ float smf[];
    float* Qs = smf;                 // [128][AST]  (pre-scaled by 1/8, tf32)
    float* Ks = Qs + QT_ * AST;      // [64][AST]
    float* Vt = Ks + 64 * AST;       // [64][AST]   V transposed: [d][key]

    const int tid  = threadIdx.x;
    const int lane = tid & 31;
    const int wid  = tid >> 5;       // 0..7
    const int grp  = lane >> 2;      // 0..7
    const int qid  = lane & 3;       // 0..3

    const int qt = blockIdx.x;
    const int bh = blockIdx.y;
    const int b  = bh >> 4;
    const int h  = bh & 15;
    const int q0 = qt * QT_;

    const int LDQ = 3 * D_;
    const float* Qb = QKV + (size_t)b * S_ * LDQ + (size_t)h * HD_;
    const float* Kb = Qb + D_;
    const float* Vb = Qb + 2 * D_;

    // ---- load Q tile (scaled by 1/sqrt(64), tf32-rounded) ----
    {
        const int r  = tid >> 1;             // 0..127
        const int c0 = (tid & 1) * 32;       // 0 or 32
        const float* src = Qb + (size_t)(q0 + r) * LDQ + c0;
        float* dst = &Qs[r * AST + c0];
#pragma unroll
        for (int i = 0; i < 8; i++) {
            float4 v = *(const float4*)(src + i * 4);
            v.x = to_tf32(v.x * 0.125f); v.y = to_tf32(v.y * 0.125f);
            v.z = to_tf32(v.z * 0.125f); v.w = to_tf32(v.w * 0.125f);
            *(float4*)(dst + i * 4) = v;
        }
    }

    const int qrow0 = wid * 16 + grp;        // warp-owned query rows
    const int* mrow0 = mask + (size_t)(b * S_ + q0 + qrow0) * S_;
    const int* mrow1 = mrow0 + 8 * S_;

    float mi0 = -1e30f, mi1 = -1e30f, li0 = 0.f, li1 = 0.f;
    float o[8][4];
#pragma unroll
    for (int nf = 0; nf < 8; nf++)
#pragma unroll
        for (int r = 0; r < 4; r++) o[nf][r] = 0.f;

    const int lr  = tid >> 2;                // KV loader row 0..63
    const int lc0 = (tid & 3) * 16;

    for (int kt = 0; kt < S_ / 64; kt++) {
        const int k0 = kt * 64;
        __syncthreads();   // prior PV reads of Ks/Vt done
        {
            const float* ksrc = Kb + (size_t)(k0 + lr) * LDQ + lc0;
            const float* vsrc = Vb + (size_t)(k0 + lr) * LDQ + lc0;
#pragma unroll
            for (int i = 0; i < 4; i++) {
                float4 kv = *(const float4*)(ksrc + i * 4);
                kv.x = to_tf32(kv.x); kv.y = to_tf32(kv.y);
                kv.z = to_tf32(kv.z); kv.w = to_tf32(kv.w);
                *(float4*)&Ks[lr * AST + lc0 + i * 4] = kv;
                float4 vv = *(const float4*)(vsrc + i * 4);
                Vt[(lc0 + i * 4 + 0) * AST + lr] = to_tf32(vv.x);
                Vt[(lc0 + i * 4 + 1) * AST + lr] = to_tf32(vv.y);
                Vt[(lc0 + i * 4 + 2) * AST + lr] = to_tf32(vv.z);
                Vt[(lc0 + i * 4 + 3) * AST + lr] = to_tf32(vv.w);
            }
        }
        __syncthreads();

        // ---- QK^T: warp computes 16x64 scores ----
        float c[8][4];
#pragma unroll
        for (int nf = 0; nf < 8; nf++)
#pragma unroll
            for (int r = 0; r < 4; r++) c[nf][r] = 0.f;

#pragma unroll
        for (int s = 0; s < 8; s++) {
            const float2 alo = *(const float2*)&Qs[qrow0 * AST + s * 8 + 2 * qid];
            const float2 ahi = *(const float2*)&Qs[(qrow0 + 8) * AST + s * 8 + 2 * qid];
            float a[4] = { alo.x, ahi.x, alo.y, ahi.y };
#pragma unroll
            for (int nf = 0; nf < 8; nf++) {
                const float2 bv = *(const float2*)&Ks[(nf * 8 + grp) * AST + s * 8 + 2 * qid];
                mma_tf32(c[nf], a, (const float*)&bv);
            }
        }

        // ---- mask (scores already scaled via Q) ----
#pragma unroll
        for (int nf = 0; nf < 8; nf++) {
            const int kc = k0 + nf * 8 + 2 * qid;
            const int2 m0 = *(const int2*)&mrow0[kc];
            const int2 m1 = *(const int2*)&mrow1[kc];
            if (m0.x == 0) c[nf][0] = -1e8f;
            if (m0.y == 0) c[nf][1] = -1e8f;
            if (m1.x == 0) c[nf][2] = -1e8f;
            if (m1.y == 0) c[nf][3] = -1e8f;
        }

        // ---- online softmax on fragments (rows grp, grp+8) ----
        float mx0 = -1e30f, mx1 = -1e30f;
#pragma unroll
        for (int nf = 0; nf < 8; nf++) {
            mx0 = fmaxf(mx0, fmaxf(c[nf][0], c[nf][1]));
            mx1 = fmaxf(mx1, fmaxf(c[nf][2], c[nf][3]));
        }
        mx0 = fmaxf(mx0, __shfl_xor_sync(0xffffffffu, mx0, 1));
        mx0 = fmaxf(mx0, __shfl_xor_sync(0xffffffffu, mx0, 2));
        mx1 = fmaxf(mx1, __shfl_xor_sync(0xffffffffu, mx1, 1));
        mx1 = fmaxf(mx1, __shfl_xor_sync(0xffffffffu, mx1, 2));

        const float mn0 = fmaxf(mi0, mx0);
        const float mn1 = fmaxf(mi1, mx1);
        const float al0 = __expf(mi0 - mn0);
        const float al1 = __expf(mi1 - mn1);

        float sum0 = 0.f, sum1 = 0.f;
#pragma unroll
        for (int nf = 0; nf < 8; nf++) {
            float e;
            e = __expf(c[nf][0] - mn0); sum0 += e; c[nf][0] = to_tf32(e);
            e = __expf(c[nf][1] - mn0); sum0 += e; c[nf][1] = to_tf32(e);
            e = __expf(c[nf][2] - mn1); sum1 += e; c[nf][2] = to_tf32(e);
            e = __expf(c[nf][3] - mn1); sum1 += e; c[nf][3] = to_tf32(e);
        }
        sum0 += __shfl_xor_sync(0xffffffffu, sum0, 1);
        sum0 += __shfl_xor_sync(0xffffffffu, sum0, 2);
        sum1 += __shfl_xor_sync(0xffffffffu, sum1, 1);
        sum1 += __shfl_xor_sync(0xffffffffu, sum1, 2);

        li0 = li0 * al0 + sum0;  mi0 = mn0;
        li1 = li1 * al1 + sum1;  mi1 = mn1;

#pragma unroll
        for (int nf = 0; nf < 8; nf++) {
            o[nf][0] *= al0; o[nf][1] *= al0;
            o[nf][2] *= al1; o[nf][3] *= al1;
        }

        // ---- PV: A = score fragments (relabeled in-register), B = Vt ----
#pragma unroll
        for (int s = 0; s < 8; s++) {
            float a[4] = { c[s][0], c[s][2], c[s][1], c[s][3] };
#pragma unroll
            for (int nf = 0; nf < 8; nf++) {
                const float2 bv = *(const float2*)&Vt[(nf * 8 + grp) * AST + s * 8 + 2 * qid];
                mma_tf32(o[nf], a, (const float*)&bv);
            }
        }
    }

    // ---- finalize: divide by l, write ctx [B,S,H,HD] (tf32-rounded) ----
    const float inv0 = 1.0f / li0;
    const float inv1 = 1.0f / li1;
    const size_t row0g = (size_t)(b * S_ + q0 + qrow0) * D_ + (size_t)h * HD_;
    const size_t row1g = row0g + (size_t)8 * D_;
#pragma unroll
    for (int nf = 0; nf < 8; nf++) {
        const int d0 = nf * 8 + 2 * qid;
        float2 v0, v1;
        v0.x = to_tf32(o[nf][0] * inv0); v0.y = to_tf32(o[nf][1] * inv0);
        v1.x = to_tf32(o[nf][2] * inv1); v1.y = to_tf32(o[nf][3] * inv1);
        *(float2*)&O[row0g + d0] = v0;
        *(float2*)&O[row1g + d0] = v1;
    }
}

// ---------------------------------------------------------------------------
// Launch.  Inputs: x, Wq, bq, Wk, bk, Wv, bv, W1, b1, W2, b2, mask
// ---------------------------------------------------------------------------
extern "C" void kernel_launch(void* const* d_in, const int* in_sizes, int n_in,
                              void* d_out, int out_size)
{
    const float* x    = (const float*)d_in[0];
    const float* Wq   = (const float*)d_in[1];
    const float* bq   = (const float*)d_in[2];
    const float* Wk   = (const float*)d_in[3];
    const float* bk   = (const float*)d_in[4];
    const float* Wv   = (const float*)d_in[5];
    const float* bv   = (const float*)d_in[6];
    const float* W1   = (const float*)d_in[7];
    const float* b1   = (const float*)d_in[8];
    const float* W2   = (const float*)d_in[9];
    const float* b2   = (const float*)d_in[10];
    const int*   mask = (const int*)d_in[11];
    float*       out  = (float*)d_out;

    float *Xp, *Wqkvp, *bqkvp, *W1p, *W2p, *QKVp, *Cp, *Hp;
    cudaGetSymbolAddress((void**)&Xp,    g_X);
    cudaGetSymbolAddress((void**)&Wqkvp, g_Wqkv);
    cudaGetSymbolAddress((void**)&bqkvp, g_bqkv);
    cudaGetSymbolAddress((void**)&W1p,   g_W1r);
    cudaGetSymbolAddress((void**)&W2p,   g_W2r);
    cudaGetSymbolAddress((void**)&QKVp,  g_QKV);
    cudaGetSymbolAddress((void**)&Cp,    g_C);
    cudaGetSymbolAddress((void**)&Hp,    g_Hid);

    cudaFuncSetAttribute(attn_tc,
                         cudaFuncAttributeMaxDynamicSharedMemorySize, ATTN_SMEM_BYTES);
    cudaFuncSetAttribute((const void*)gemm_tc<false,false>,
                         cudaFuncAttributeMaxDynamicSharedMemorySize, GEMM_SMEM_BYTES);
    cudaFuncSetAttribute((const void*)gemm_tc<true,true>,
                         cudaFuncAttributeMaxDynamicSharedMemorySize, GEMM_SMEM_BYTES);

    const dim3 blk(256);

    // ---- prep: round inputs to tf32 once ----
    const int T = 256;
    round_copy4<<<(M_ * D_ / 4 + T - 1) / T, T>>>(x,  Xp,              M_ * D_ / 4);
    round_copy4<<<(D_ * D_ / 4 + T - 1) / T, T>>>(Wq, Wqkvp,           D_ * D_ / 4);
    round_copy4<<<(D_ * D_ / 4 + T - 1) / T, T>>>(Wk, Wqkvp + D_ * D_, D_ * D_ / 4);
    round_copy4<<<(D_ * D_ / 4 + T - 1) / T, T>>>(Wv, Wqkvp + 2 * D_ * D_, D_ * D_ / 4);
    round_copy4<<<(2 * D_ * D_ / 4 + T - 1) / T, T>>>(W1, W1p, 2 * D_ * D_ / 4);
    round_copy4<<<(2 * D_ * D_ / 4 + T - 1) / T, T>>>(W2, W2p, 2 * D_ * D_ / 4);
    concat_bias<<<(3 * D_ + T - 1) / T, T>>>(bq, bk, bv, bqkvp);

    // ---- fused QKV projection: [4096,3072] ----
    gemm_tc<false,false><<<dim3(3 * D_ / 128, M_ / 128), blk, GEMM_SMEM_BYTES>>>(
        Xp, Wqkvp, bqkvp, QKVp, M_, 3 * D_, D_);

    // ---- attention (tensor-core) ----
    attn_tc<<<dim3(S_ / QT_, B_ * H_), blk, ATTN_SMEM_BYTES>>>(QKVp, mask, Cp);

    // ---- MLP ----
    gemm_tc<true,true ><<<dim3(2 * D_ / 128, M_ / 128), blk, GEMM_SMEM_BYTES>>>(
        Cp, W1p, b1, Hp, M_, 2 * D_, D_);
    gemm_tc<false,false><<<dim3(D_ / 128, M_ / 128), blk, GEMM_SMEM_BYTES>>>(
        Hp, W2p, b2, out, M_, D_, 2 * D_);
}

// round 6
// speedup vs baseline: 2.9842x; 1.2590x over previous
#include <cuda_runtime.h>
#include <stdint.h>

#define B_  4
#define S_  1024
#define D_  1024
#define H_  16
#define HD_ 64
#define M_  (B_ * S_)     // 4096

// ---------------------------------------------------------------------------
// Scratch (device globals)
// ---------------------------------------------------------------------------
__device__ __align__(16) float g_X   [(size_t)M_ * D_];
__device__ __align__(16) float g_Wqkv[(size_t)3 * D_ * D_];
__device__ __align__(16) float g_bqkv[3 * D_];
__device__ __align__(16) float g_W1r [(size_t)2 * D_ * D_];
__device__ __align__(16) float g_W2r [(size_t)2 * D_ * D_];
__device__ __align__(16) float g_QKV [(size_t)M_ * 3 * D_];
__device__ __align__(16) float g_C   [(size_t)M_ * D_];
__device__ __align__(16) float g_Hid [(size_t)M_ * 2 * D_];

// ---------------------------------------------------------------------------
__device__ __forceinline__ float to_tf32(float x) {
    uint32_t u;
    asm("cvt.rna.tf32.f32 %0, %1;" : "=r"(u) : "f"(x));
    return __uint_as_float(u);
}

__device__ __forceinline__ void mma_tf32(float* c, const float* a, const float* b) {
    asm volatile(
        "mma.sync.aligned.m16n8k8.row.col.f32.tf32.tf32.f32 "
        "{%0,%1,%2,%3}, {%4,%5,%6,%7}, {%8,%9}, {%0,%1,%2,%3};\n"
        : "+f"(c[0]), "+f"(c[1]), "+f"(c[2]), "+f"(c[3])
        : "r"(__float_as_uint(a[0])), "r"(__float_as_uint(a[1])),
          "r"(__float_as_uint(a[2])), "r"(__float_as_uint(a[3])),
          "r"(__float_as_uint(b[0])), "r"(__float_as_uint(b[1])));
}

__device__ __forceinline__ uint32_t smem_u32(const void* p) {
    uint32_t a;
    asm("{ .reg .u64 t; cvta.to.shared.u64 t, %1; cvt.u32.u64 %0, t; }"
        : "=r"(a) : "l"(p));
    return a;
}

__device__ __forceinline__ void cp_async16(uint32_t dst, const void* src) {
    asm volatile("cp.async.cg.shared.global [%0], [%1], 16;"
                 :: "r"(dst), "l"(src) : "memory");
}

// ---------------------------------------------------------------------------
// Prep kernels
// ---------------------------------------------------------------------------
__global__ void round_copy4(const float* __restrict__ src, float* __restrict__ dst, int n4) {
    const int i = blockIdx.x * blockDim.x + threadIdx.x;
    if (i < n4) {
        float4 v = ((const float4*)src)[i];
        v.x = to_tf32(v.x); v.y = to_tf32(v.y);
        v.z = to_tf32(v.z); v.w = to_tf32(v.w);
        ((float4*)dst)[i] = v;
    }
}

__global__ void concat_bias(const float* __restrict__ a, const float* __restrict__ b,
                            const float* __restrict__ c, float* __restrict__ dst) {
    const int i = blockIdx.x * blockDim.x + threadIdx.x;
    if (i < 3 * D_)
        dst[i] = (i < D_) ? a[i] : ((i < 2 * D_) ? b[i - D_] : c[i - 2 * D_]);
}

// ---------------------------------------------------------------------------
// Tensor-core GEMM (tf32, inputs pre-rounded), cp.async 4-stage pipeline:
//   C[m,n] = sum_k A[m,k]*B[n,k] + bias[n]   ("NT", row-major)
// 128x128 tile, K-tile 16, 256 threads, warp tile 64x32.
// Smem row stride 24 floats: fragment LDS.64 conflict-free; cp.async copies
// raw 16B chunks into the padded layout verbatim.
// ---------------------------------------------------------------------------
#define ASTR 24
#define STG_BYTES (128 * ASTR * 4)           // 12,288 per matrix per stage
#define STAGE_BYTES (2 * STG_BYTES)          // 24,576 (A then B)
#define NSTAGE 4
#define GEMM_SMEM_BYTES (NSTAGE * STAGE_BYTES)  // 98,304

template <bool RELU, bool ROUND_OUT>
__global__ __launch_bounds__(256, 2)
void gemm_tc(const float* __restrict__ A, const float* __restrict__ Bm,
             const float* __restrict__ bias, float* __restrict__ C,
             int M, int N, int K)
{
    extern __shared__ __align__(16) char smc[];
    float* smf = (float*)smc;
    const uint32_t sb = smem_u32(smc);

    const int tid  = threadIdx.x;
    const int lane = tid & 31;
    const int wid  = tid >> 5;
    const int wm   = wid >> 2;
    const int wn   = wid & 3;
    const int grp  = lane >> 2;
    const int qid  = lane & 3;

    const int bm = blockIdx.y * 128;
    const int bn = blockIdx.x * 128;

    // loader mapping: 2 chunk-jobs per thread per matrix
    const int lrow0 = tid >> 2;              // 0..63
    const int lc4   = (tid & 3) * 4;         // 0,4,8,12
    const float* AgBase = A  + (size_t)bm * K;
    const float* BgBase = Bm + (size_t)bn * K;

    auto issue_stage = [&](int stage, int buf) {
        const int k0 = stage * 16;
        const uint32_t sA = sb + (uint32_t)buf * STAGE_BYTES;
        const uint32_t sB = sA + STG_BYTES;
#pragma unroll
        for (int i = 0; i < 2; i++) {
            const int row = lrow0 + 64 * i;
            const uint32_t doff = (uint32_t)(row * ASTR + lc4) * 4;
            cp_async16(sA + doff, AgBase + (size_t)row * K + k0 + lc4);
            cp_async16(sB + doff, BgBase + (size_t)row * K + k0 + lc4);
        }
        asm volatile("cp.async.commit_group;" ::: "memory");
    };

    float acc[4][4][4];
#pragma unroll
    for (int i = 0; i < 4; i++)
#pragma unroll
        for (int j = 0; j < 4; j++)
#pragma unroll
            for (int r = 0; r < 4; r++) acc[i][j][r] = 0.f;

    const int KT = K / 16;

    issue_stage(0, 0);
    issue_stage(1, 1);
    issue_stage(2, 2);

    for (int kt = 0; kt < KT; kt++) {
        const int buf = kt & (NSTAGE - 1);

        // wait for stage kt's data
        if (kt < KT - 2)
            asm volatile("cp.async.wait_group 2;" ::: "memory");
        else if (kt == KT - 2)
            asm volatile("cp.async.wait_group 1;" ::: "memory");
        else
            asm volatile("cp.async.wait_group 0;" ::: "memory");
        __syncthreads();

        const float* Asb = smf + (size_t)buf * (STAGE_BYTES / 4);
        const float* Bsb = Asb + STG_BYTES / 4;

#pragma unroll
        for (int s = 0; s < 2; s++) {
            float a[4][4];
#pragma unroll
            for (int mf = 0; mf < 4; mf++) {
                const int row = wm * 64 + mf * 16 + grp;
                const float2 lo = *(const float2*)&Asb[row * ASTR + s * 8 + 2 * qid];
                const float2 hi = *(const float2*)&Asb[(row + 8) * ASTR + s * 8 + 2 * qid];
                a[mf][0] = lo.x; a[mf][1] = hi.x; a[mf][2] = lo.y; a[mf][3] = hi.y;
            }
            float b[4][2];
#pragma unroll
            for (int nf = 0; nf < 4; nf++) {
                const int row = wn * 32 + nf * 8 + grp;
                const float2 bv = *(const float2*)&Bsb[row * ASTR + s * 8 + 2 * qid];
                b[nf][0] = bv.x; b[nf][1] = bv.y;
            }
#pragma unroll
            for (int mf = 0; mf < 4; mf++)
#pragma unroll
                for (int nf = 0; nf < 4; nf++)
                    mma_tf32(acc[mf][nf], a[mf], b[nf]);
        }

        // issue stage kt+3 into the buffer freed by stage kt-1
        if (kt + 3 < KT)
            issue_stage(kt + 3, (kt + 3) & (NSTAGE - 1));
    }

    // Epilogue: bias (+ReLU) (+round), float2 stores
#pragma unroll
    for (int mf = 0; mf < 4; mf++) {
#pragma unroll
        for (int nf = 0; nf < 4; nf++) {
            const int m0 = bm + wm * 64 + mf * 16 + grp;
            const int n0 = bn + wn * 32 + nf * 8 + 2 * qid;
            const float bx = bias[n0], by = bias[n0 + 1];
            float2 v0, v1;
            v0.x = acc[mf][nf][0] + bx; v0.y = acc[mf][nf][1] + by;
            v1.x = acc[mf][nf][2] + bx; v1.y = acc[mf][nf][3] + by;
            if (RELU) {
                v0.x = fmaxf(v0.x, 0.f); v0.y = fmaxf(v0.y, 0.f);
                v1.x = fmaxf(v1.x, 0.f); v1.y = fmaxf(v1.y, 0.f);
            }
            if (ROUND_OUT) {
                v0.x = to_tf32(v0.x); v0.y = to_tf32(v0.y);
                v1.x = to_tf32(v1.x); v1.y = to_tf32(v1.y);
            }
            *(float2*)&C[(size_t)m0 * N + n0]       = v0;
            *(float2*)&C[(size_t)(m0 + 8) * N + n0] = v1;
        }
    }
}

// ---------------------------------------------------------------------------
// Tensor-core flash attention (tf32 mma, register-fragment softmax) — R4.
// ---------------------------------------------------------------------------
#define AST 68
#define QT_ 128
#define ATTN_SMEM_BYTES ((QT_ + 64 + 64) * AST * 4)

__global__ __launch_bounds__(256, 2)
void attn_tc(const float* __restrict__ QKV, const int* __restrict__ mask,
             float* __restrict__ O)
{
    extern __shared__ float smf[];
    float* Qs = smf;
    float* Ks = Qs + QT_ * AST;
    float* Vt = Ks + 64 * AST;

    const int tid  = threadIdx.x;
    const int lane = tid & 31;
    const int wid  = tid >> 5;
    const int grp  = lane >> 2;
    const int qid  = lane & 3;

    const int qt = blockIdx.x;
    const int bh = blockIdx.y;
    const int b  = bh >> 4;
    const int h  = bh & 15;
    const int q0 = qt * QT_;

    const int LDQ = 3 * D_;
    const float* Qb = QKV + (size_t)b * S_ * LDQ + (size_t)h * HD_;
    const float* Kb = Qb + D_;
    const float* Vb = Qb + 2 * D_;

    {
        const int r  = tid >> 1;
        const int c0 = (tid & 1) * 32;
        const float* src = Qb + (size_t)(q0 + r) * LDQ + c0;
        float* dst = &Qs[r * AST + c0];
#pragma unroll
        for (int i = 0; i < 8; i++) {
            float4 v = *(const float4*)(src + i * 4);
            v.x = to_tf32(v.x * 0.125f); v.y = to_tf32(v.y * 0.125f);
            v.z = to_tf32(v.z * 0.125f); v.w = to_tf32(v.w * 0.125f);
            *(float4*)(dst + i * 4) = v;
        }
    }

    const int qrow0 = wid * 16 + grp;
    const int* mrow0 = mask + (size_t)(b * S_ + q0 + qrow0) * S_;
    const int* mrow1 = mrow0 + 8 * S_;

    float mi0 = -1e30f, mi1 = -1e30f, li0 = 0.f, li1 = 0.f;
    float o[8][4];
#pragma unroll
    for (int nf = 0; nf < 8; nf++)
#pragma unroll
        for (int r = 0; r < 4; r++) o[nf][r] = 0.f;

    const int lr  = tid >> 2;
    const int lc0 = (tid & 3) * 16;

    for (int kt = 0; kt < S_ / 64; kt++) {
        const int k0 = kt * 64;
        __syncthreads();
        {
            const float* ksrc = Kb + (size_t)(k0 + lr) * LDQ + lc0;
            const float* vsrc = Vb + (size_t)(k0 + lr) * LDQ + lc0;
#pragma unroll
            for (int i = 0; i < 4; i++) {
                float4 kv = *(const float4*)(ksrc + i * 4);
                kv.x = to_tf32(kv.x); kv.y = to_tf32(kv.y);
                kv.z = to_tf32(kv.z); kv.w = to_tf32(kv.w);
                *(float4*)&Ks[lr * AST + lc0 + i * 4] = kv;
                float4 vv = *(const float4*)(vsrc + i * 4);
                Vt[(lc0 + i * 4 + 0) * AST + lr] = to_tf32(vv.x);
                Vt[(lc0 + i * 4 + 1) * AST + lr] = to_tf32(vv.y);
                Vt[(lc0 + i * 4 + 2) * AST + lr] = to_tf32(vv.z);
                Vt[(lc0 + i * 4 + 3) * AST + lr] = to_tf32(vv.w);
            }
        }
        __syncthreads();

        float c[8][4];
#pragma unroll
        for (int nf = 0; nf < 8; nf++)
#pragma unroll
            for (int r = 0; r < 4; r++) c[nf][r] = 0.f;

#pragma unroll
        for (int s = 0; s < 8; s++) {
            const float2 alo = *(const float2*)&Qs[qrow0 * AST + s * 8 + 2 * qid];
            const float2 ahi = *(const float2*)&Qs[(qrow0 + 8) * AST + s * 8 + 2 * qid];
            float a[4] = { alo.x, ahi.x, alo.y, ahi.y };
#pragma unroll
            for (int nf = 0; nf < 8; nf++) {
                const float2 bv = *(const float2*)&Ks[(nf * 8 + grp) * AST + s * 8 + 2 * qid];
                mma_tf32(c[nf], a, (const float*)&bv);
            }
        }

#pragma unroll
        for (int nf = 0; nf < 8; nf++) {
            const int kc = k0 + nf * 8 + 2 * qid;
            const int2 m0 = *(const int2*)&mrow0[kc];
            const int2 m1 = *(const int2*)&mrow1[kc];
            if (m0.x == 0) c[nf][0] = -1e8f;
            if (m0.y == 0) c[nf][1] = -1e8f;
            if (m1.x == 0) c[nf][2] = -1e8f;
            if (m1.y == 0) c[nf][3] = -1e8f;
        }

        float mx0 = -1e30f, mx1 = -1e30f;
#pragma unroll
        for (int nf = 0; nf < 8; nf++) {
            mx0 = fmaxf(mx0, fmaxf(c[nf][0], c[nf][1]));
            mx1 = fmaxf(mx1, fmaxf(c[nf][2], c[nf][3]));
        }
        mx0 = fmaxf(mx0, __shfl_xor_sync(0xffffffffu, mx0, 1));
        mx0 = fmaxf(mx0, __shfl_xor_sync(0xffffffffu, mx0, 2));
        mx1 = fmaxf(mx1, __shfl_xor_sync(0xffffffffu, mx1, 1));
        mx1 = fmaxf(mx1, __shfl_xor_sync(0xffffffffu, mx1, 2));

        const float mn0 = fmaxf(mi0, mx0);
        const float mn1 = fmaxf(mi1, mx1);
        const float al0 = __expf(mi0 - mn0);
        const float al1 = __expf(mi1 - mn1);

        float sum0 = 0.f, sum1 = 0.f;
#pragma unroll
        for (int nf = 0; nf < 8; nf++) {
            float e;
            e = __expf(c[nf][0] - mn0); sum0 += e; c[nf][0] = to_tf32(e);
            e = __expf(c[nf][1] - mn0); sum0 += e; c[nf][1] = to_tf32(e);
            e = __expf(c[nf][2] - mn1); sum1 += e; c[nf][2] = to_tf32(e);
            e = __expf(c[nf][3] - mn1); sum1 += e; c[nf][3] = to_tf32(e);
        }
        sum0 += __shfl_xor_sync(0xffffffffu, sum0, 1);
        sum0 += __shfl_xor_sync(0xffffffffu, sum0, 2);
        sum1 += __shfl_xor_sync(0xffffffffu, sum1, 1);
        sum1 += __shfl_xor_sync(0xffffffffu, sum1, 2);

        li0 = li0 * al0 + sum0;  mi0 = mn0;
        li1 = li1 * al1 + sum1;  mi1 = mn1;

#pragma unroll
        for (int nf = 0; nf < 8; nf++) {
            o[nf][0] *= al0; o[nf][1] *= al0;
            o[nf][2] *= al1; o[nf][3] *= al1;
        }

#pragma unroll
        for (int s = 0; s < 8; s++) {
            float a[4] = { c[s][0], c[s][2], c[s][1], c[s][3] };
#pragma unroll
            for (int nf = 0; nf < 8; nf++) {
                const float2 bv = *(const float2*)&Vt[(nf * 8 + grp) * AST + s * 8 + 2 * qid];
                mma_tf32(o[nf], a, (const float*)&bv);
            }
        }
    }

    const float inv0 = 1.0f / li0;
    const float inv1 = 1.0f / li1;
    const size_t row0g = (size_t)(b * S_ + q0 + qrow0) * D_ + (size_t)h * HD_;
    const size_t row1g = row0g + (size_t)8 * D_;
#pragma unroll
    for (int nf = 0; nf < 8; nf++) {
        const int d0 = nf * 8 + 2 * qid;
        float2 v0, v1;
        v0.x = to_tf32(o[nf][0] * inv0); v0.y = to_tf32(o[nf][1] * inv0);
        v1.x = to_tf32(o[nf][2] * inv1); v1.y = to_tf32(o[nf][3] * inv1);
        *(float2*)&O[row0g + d0] = v0;
        *(float2*)&O[row1g + d0] = v1;
    }
}

// ---------------------------------------------------------------------------
// Launch.  Inputs: x, Wq, bq, Wk, bk, Wv, bv, W1, b1, W2, b2, mask
// ---------------------------------------------------------------------------
extern "C" void kernel_launch(void* const* d_in, const int* in_sizes, int n_in,
                              void* d_out, int out_size)
{
    const float* x    = (const float*)d_in[0];
    const float* Wq   = (const float*)d_in[1];
    const float* bq   = (const float*)d_in[2];
    const float* Wk   = (const float*)d_in[3];
    const float* bk   = (const float*)d_in[4];
    const float* Wv   = (const float*)d_in[5];
    const float* bv   = (const float*)d_in[6];
    const float* W1   = (const float*)d_in[7];
    const float* b1   = (const float*)d_in[8];
    const float* W2   = (const float*)d_in[9];
    const float* b2   = (const float*)d_in[10];
    const int*   mask = (const int*)d_in[11];
    float*       out  = (float*)d_out;

    float *Xp, *Wqkvp, *bqkvp, *W1p, *W2p, *QKVp, *Cp, *Hp;
    cudaGetSymbolAddress((void**)&Xp,    g_X);
    cudaGetSymbolAddress((void**)&Wqkvp, g_Wqkv);
    cudaGetSymbolAddress((void**)&bqkvp, g_bqkv);
    cudaGetSymbolAddress((void**)&W1p,   g_W1r);
    cudaGetSymbolAddress((void**)&W2p,   g_W2r);
    cudaGetSymbolAddress((void**)&QKVp,  g_QKV);
    cudaGetSymbolAddress((void**)&Cp,    g_C);
    cudaGetSymbolAddress((void**)&Hp,    g_Hid);

    cudaFuncSetAttribute(attn_tc,
                         cudaFuncAttributeMaxDynamicSharedMemorySize, ATTN_SMEM_BYTES);
    cudaFuncSetAttribute((const void*)gemm_tc<false, false>,
                         cudaFuncAttributeMaxDynamicSharedMemorySize, GEMM_SMEM_BYTES);
    cudaFuncSetAttribute((const void*)gemm_tc<true, true>,
                         cudaFuncAttributeMaxDynamicSharedMemorySize, GEMM_SMEM_BYTES);

    const dim3 blk(256);

    // ---- prep: round inputs to tf32 once ----
    const int T = 256;
    round_copy4<<<(M_ * D_ / 4 + T - 1) / T, T>>>(x,  Xp,              M_ * D_ / 4);
    round_copy4<<<(D_ * D_ / 4 + T - 1) / T, T>>>(Wq, Wqkvp,           D_ * D_ / 4);
    round_copy4<<<(D_ * D_ / 4 + T - 1) / T, T>>>(Wk, Wqkvp + D_ * D_, D_ * D_ / 4);
    round_copy4<<<(D_ * D_ / 4 + T - 1) / T, T>>>(Wv, Wqkvp + 2 * D_ * D_, D_ * D_ / 4);
    round_copy4<<<(2 * D_ * D_ / 4 + T - 1) / T, T>>>(W1, W1p, 2 * D_ * D_ / 4);
    round_copy4<<<(2 * D_ * D_ / 4 + T - 1) / T, T>>>(W2, W2p, 2 * D_ * D_ / 4);
    concat_bias<<<(3 * D_ + T - 1) / T, T>>>(bq, bk, bv, bqkvp);

    // ---- fused QKV projection: [4096,3072] ----
    gemm_tc<false, false><<<dim3(3 * D_ / 128, M_ / 128), blk, GEMM_SMEM_BYTES>>>(
        Xp, Wqkvp, bqkvp, QKVp, M_, 3 * D_, D_);

    // ---- attention (tensor-core) ----
    attn_tc<<<dim3(S_ / QT_, B_ * H_), blk, ATTN_SMEM_BYTES>>>(QKVp, mask, Cp);

    // ---- MLP ----
    gemm_tc<true, true><<<dim3(2 * D_ / 128, M_ / 128), blk, GEMM_SMEM_BYTES>>>(
        Cp, W1p, b1, Hp, M_, 2 * D_, D_);
    gemm_tc<false, false><<<dim3(D_ / 128, M_ / 128), blk, GEMM_SMEM_BYTES>>>(
        Hp, W2p, b2, out, M_, D_, 2 * D_);
}

// round 7
// speedup vs baseline: 3.2792x; 1.0989x over previous
#include <cuda_runtime.h>
#include <stdint.h>

#define B_  4
#define S_  1024
#define D_  1024
#define H_  16
#define HD_ 64
#define M_  (B_ * S_)     // 4096

// ---------------------------------------------------------------------------
// Scratch (device globals)
// ---------------------------------------------------------------------------
__device__ __align__(16) float g_X   [(size_t)M_ * D_];
__device__ __align__(16) float g_Wqkv[(size_t)3 * D_ * D_];
__device__ __align__(16) float g_bqkv[3 * D_];
__device__ __align__(16) float g_W1r [(size_t)2 * D_ * D_];
__device__ __align__(16) float g_W2r [(size_t)2 * D_ * D_];
__device__ __align__(16) float g_QKV [(size_t)M_ * 3 * D_];
__device__ __align__(16) float g_C   [(size_t)M_ * D_];
__device__ __align__(16) float g_Hid [(size_t)M_ * 2 * D_];

// ---------------------------------------------------------------------------
__device__ __forceinline__ float to_tf32(float x) {
    uint32_t u;
    asm("cvt.rna.tf32.f32 %0, %1;" : "=r"(u) : "f"(x));
    return __uint_as_float(u);
}

__device__ __forceinline__ void mma_tf32(float* c, const float* a, const float* b) {
    asm volatile(
        "mma.sync.aligned.m16n8k8.row.col.f32.tf32.tf32.f32 "
        "{%0,%1,%2,%3}, {%4,%5,%6,%7}, {%8,%9}, {%0,%1,%2,%3};\n"
        : "+f"(c[0]), "+f"(c[1]), "+f"(c[2]), "+f"(c[3])
        : "r"(__float_as_uint(a[0])), "r"(__float_as_uint(a[1])),
          "r"(__float_as_uint(a[2])), "r"(__float_as_uint(a[3])),
          "r"(__float_as_uint(b[0])), "r"(__float_as_uint(b[1])));
}

__device__ __forceinline__ uint32_t smem_u32(const void* p) {
    uint32_t a;
    asm("{ .reg .u64 t; cvta.to.shared.u64 t, %1; cvt.u32.u64 %0, t; }"
        : "=r"(a) : "l"(p));
    return a;
}

__device__ __forceinline__ void cp_async16(uint32_t dst, const void* src) {
    asm volatile("cp.async.cg.shared.global [%0], [%1], 16;"
                 :: "r"(dst), "l"(src) : "memory");
}

// ---------------------------------------------------------------------------
// Prep kernels
// ---------------------------------------------------------------------------
__global__ void round_copy4(const float* __restrict__ src, float* __restrict__ dst, int n4) {
    const int i = blockIdx.x * blockDim.x + threadIdx.x;
    if (i < n4) {
        float4 v = ((const float4*)src)[i];
        v.x = to_tf32(v.x); v.y = to_tf32(v.y);
        v.z = to_tf32(v.z); v.w = to_tf32(v.w);
        ((float4*)dst)[i] = v;
    }
}

__global__ void concat_bias(const float* __restrict__ a, const float* __restrict__ b,
                            const float* __restrict__ c, float* __restrict__ dst) {
    const int i = blockIdx.x * blockDim.x + threadIdx.x;
    if (i < 3 * D_)
        dst[i] = (i < D_) ? a[i] : ((i < 2 * D_) ? b[i - D_] : c[i - 2 * D_]);
}

// ---------------------------------------------------------------------------
// Tensor-core GEMM (tf32, inputs pre-rounded), cp.async 4-stage pipeline.
//   C[m,n] = sum_k A[m,k]*B[n,k] + bias[n]   ("NT", row-major)
// Epilogue modes: RELU; ROUND_OUT (tf32-round stores); QKV_SCALE (multiply
// columns n<1024 by 0.125 before rounding — Q pre-scaling for attention).
// ---------------------------------------------------------------------------
#define ASTR 24
#define STG_BYTES (128 * ASTR * 4)
#define STAGE_BYTES (2 * STG_BYTES)
#define NSTAGE 4
#define GEMM_SMEM_BYTES (NSTAGE * STAGE_BYTES)  // 98,304

template <bool RELU, bool ROUND_OUT, bool QKV_SCALE>
__global__ __launch_bounds__(256, 2)
void gemm_tc(const float* __restrict__ A, const float* __restrict__ Bm,
             const float* __restrict__ bias, float* __restrict__ C,
             int M, int N, int K)
{
    extern __shared__ __align__(16) char smc[];
    float* smf = (float*)smc;
    const uint32_t sb = smem_u32(smc);

    const int tid  = threadIdx.x;
    const int lane = tid & 31;
    const int wid  = tid >> 5;
    const int wm   = wid >> 2;
    const int wn   = wid & 3;
    const int grp  = lane >> 2;
    const int qid  = lane & 3;

    const int bm = blockIdx.y * 128;
    const int bn = blockIdx.x * 128;

    const int lrow0 = tid >> 2;
    const int lc4   = (tid & 3) * 4;
    const float* AgBase = A  + (size_t)bm * K;
    const float* BgBase = Bm + (size_t)bn * K;

    auto issue_stage = [&](int stage, int buf) {
        const int k0 = stage * 16;
        const uint32_t sA = sb + (uint32_t)buf * STAGE_BYTES;
        const uint32_t sB = sA + STG_BYTES;
#pragma unroll
        for (int i = 0; i < 2; i++) {
            const int row = lrow0 + 64 * i;
            const uint32_t doff = (uint32_t)(row * ASTR + lc4) * 4;
            cp_async16(sA + doff, AgBase + (size_t)row * K + k0 + lc4);
            cp_async16(sB + doff, BgBase + (size_t)row * K + k0 + lc4);
        }
        asm volatile("cp.async.commit_group;" ::: "memory");
    };

    float acc[4][4][4];
#pragma unroll
    for (int i = 0; i < 4; i++)
#pragma unroll
        for (int j = 0; j < 4; j++)
#pragma unroll
            for (int r = 0; r < 4; r++) acc[i][j][r] = 0.f;

    const int KT = K / 16;

    issue_stage(0, 0);
    issue_stage(1, 1);
    issue_stage(2, 2);

    for (int kt = 0; kt < KT; kt++) {
        const int buf = kt & (NSTAGE - 1);

        if (kt < KT - 2)
            asm volatile("cp.async.wait_group 2;" ::: "memory");
        else if (kt == KT - 2)
            asm volatile("cp.async.wait_group 1;" ::: "memory");
        else
            asm volatile("cp.async.wait_group 0;" ::: "memory");
        __syncthreads();

        const float* Asb = smf + (size_t)buf * (STAGE_BYTES / 4);
        const float* Bsb = Asb + STG_BYTES / 4;

#pragma unroll
        for (int s = 0; s < 2; s++) {
            float a[4][4];
#pragma unroll
            for (int mf = 0; mf < 4; mf++) {
                const int row = wm * 64 + mf * 16 + grp;
                const float2 lo = *(const float2*)&Asb[row * ASTR + s * 8 + 2 * qid];
                const float2 hi = *(const float2*)&Asb[(row + 8) * ASTR + s * 8 + 2 * qid];
                a[mf][0] = lo.x; a[mf][1] = hi.x; a[mf][2] = lo.y; a[mf][3] = hi.y;
            }
            float b[4][2];
#pragma unroll
            for (int nf = 0; nf < 4; nf++) {
                const int row = wn * 32 + nf * 8 + grp;
                const float2 bv = *(const float2*)&Bsb[row * ASTR + s * 8 + 2 * qid];
                b[nf][0] = bv.x; b[nf][1] = bv.y;
            }
#pragma unroll
            for (int mf = 0; mf < 4; mf++)
#pragma unroll
                for (int nf = 0; nf < 4; nf++)
                    mma_tf32(acc[mf][nf], a[mf], b[nf]);
        }

        if (kt + 3 < KT)
            issue_stage(kt + 3, (kt + 3) & (NSTAGE - 1));
    }

#pragma unroll
    for (int mf = 0; mf < 4; mf++) {
#pragma unroll
        for (int nf = 0; nf < 4; nf++) {
            const int m0 = bm + wm * 64 + mf * 16 + grp;
            const int n0 = bn + wn * 32 + nf * 8 + 2 * qid;
            const float bx = bias[n0], by = bias[n0 + 1];
            float2 v0, v1;
            v0.x = acc[mf][nf][0] + bx; v0.y = acc[mf][nf][1] + by;
            v1.x = acc[mf][nf][2] + bx; v1.y = acc[mf][nf][3] + by;
            if (RELU) {
                v0.x = fmaxf(v0.x, 0.f); v0.y = fmaxf(v0.y, 0.f);
                v1.x = fmaxf(v1.x, 0.f); v1.y = fmaxf(v1.y, 0.f);
            }
            if (QKV_SCALE) {
                const float sc = (n0 < D_) ? 0.125f : 1.0f;  // Q columns pre-scaled
                v0.x *= sc; v0.y *= sc; v1.x *= sc; v1.y *= sc;
            }
            if (ROUND_OUT) {
                v0.x = to_tf32(v0.x); v0.y = to_tf32(v0.y);
                v1.x = to_tf32(v1.x); v1.y = to_tf32(v1.y);
            }
            *(float2*)&C[(size_t)m0 * N + n0]       = v0;
            *(float2*)&C[(size_t)(m0 + 8) * N + n0] = v1;
        }
    }
}

// ---------------------------------------------------------------------------
// Tensor-core flash attention, cp.async K/V double-buffer, V row-major.
// QKV entries are pre-scaled (Q) and tf32-rounded by the QKV GEMM epilogue,
// so all loads here are raw byte copies.
// ---------------------------------------------------------------------------
#define AST 68
#define QT_ 128
#define KVSTG (64 * AST * 4)                          // 17,408 B per stage
#define ATTN_SMEM_BYTES (QT_ * AST * 4 + 4 * KVSTG)   // 104,448 B

__global__ __launch_bounds__(256, 2)
void attn_tc(const float* __restrict__ QKV, const int* __restrict__ mask,
             float* __restrict__ O)
{
    extern __shared__ float smf[];
    float* Qs = smf;                              // [128][AST]
    const uint32_t sb   = smem_u32(smf);
    const uint32_t sbK  = sb + QT_ * AST * 4;     // 2 stages of K
    const uint32_t sbV  = sbK + 2 * KVSTG;        // 2 stages of V (row-major)

    const int tid  = threadIdx.x;
    const int lane = tid & 31;
    const int wid  = tid >> 5;
    const int grp  = lane >> 2;
    const int qid  = lane & 3;

    const int qt = blockIdx.x;
    const int bh = blockIdx.y;
    const int b  = bh >> 4;
    const int h  = bh & 15;
    const int q0 = qt * QT_;

    const int LDQ = 3 * D_;
    const float* Qb = QKV + (size_t)b * S_ * LDQ + (size_t)h * HD_;
    const float* Kb = Qb + D_;
    const float* Vb = Qb + 2 * D_;

    auto issue_kv = [&](int kt, int buf) {
        const int k0g = kt * 64;
        const uint32_t sK = sbK + (uint32_t)buf * KVSTG;
        const uint32_t sV = sbV + (uint32_t)buf * KVSTG;
#pragma unroll
        for (int i = 0; i < 4; i++) {
            const int c   = tid + 256 * i;        // 0..1023
            const int row = c >> 4;               // 0..63
            const int col = (c & 15) * 4;         // 0..60
            const uint32_t doff = (uint32_t)(row * AST + col) * 4;
            cp_async16(sK + doff, Kb + (size_t)(k0g + row) * LDQ + col);
            cp_async16(sV + doff, Vb + (size_t)(k0g + row) * LDQ + col);
        }
        asm volatile("cp.async.commit_group;" ::: "memory");
    };

    issue_kv(0, 0);

    // Q tile: raw copy (pre-scaled + rounded upstream)
    {
        const int r  = tid >> 1;
        const int c0 = (tid & 1) * 32;
        const float* src = Qb + (size_t)(q0 + r) * LDQ + c0;
        float* dst = &Qs[r * AST + c0];
#pragma unroll
        for (int i = 0; i < 8; i++)
            *(float4*)(dst + i * 4) = *(const float4*)(src + i * 4);
    }

    const int qrow0 = wid * 16 + grp;
    const int* mrow0 = mask + (size_t)(b * S_ + q0 + qrow0) * S_;
    const int* mrow1 = mrow0 + 8 * S_;

    float mi0 = -1e30f, mi1 = -1e30f, li0 = 0.f, li1 = 0.f;
    float o[8][4];
#pragma unroll
    for (int nf = 0; nf < 8; nf++)
#pragma unroll
        for (int r = 0; r < 4; r++) o[nf][r] = 0.f;

    for (int kt = 0; kt < S_ / 64; kt++) {
        const int buf = kt & 1;
        const int k0  = kt * 64;

        asm volatile("cp.async.wait_group 0;" ::: "memory");
        __syncthreads();   // stage kt visible to all; prior compute done

        if (kt + 1 < S_ / 64)
            issue_kv(kt + 1, buf ^ 1);   // overlaps with compute below

        const float* Ksb = smf + (QT_ * AST) + (size_t)buf * (KVSTG / 4);
        const float* Vsb = smf + (QT_ * AST) + 2 * (KVSTG / 4) + (size_t)buf * (KVSTG / 4);

        // ---- QK^T ----
        float c[8][4];
#pragma unroll
        for (int nf = 0; nf < 8; nf++)
#pragma unroll
            for (int r = 0; r < 4; r++) c[nf][r] = 0.f;

#pragma unroll
        for (int s = 0; s < 8; s++) {
            const float2 alo = *(const float2*)&Qs[qrow0 * AST + s * 8 + 2 * qid];
            const float2 ahi = *(const float2*)&Qs[(qrow0 + 8) * AST + s * 8 + 2 * qid];
            float a[4] = { alo.x, ahi.x, alo.y, ahi.y };
#pragma unroll
            for (int nf = 0; nf < 8; nf++) {
                const float2 bv = *(const float2*)&Ksb[(nf * 8 + grp) * AST + s * 8 + 2 * qid];
                mma_tf32(c[nf], a, (const float*)&bv);
            }
        }

        // ---- mask ----
#pragma unroll
        for (int nf = 0; nf < 8; nf++) {
            const int kc = k0 + nf * 8 + 2 * qid;
            const int2 m0 = *(const int2*)&mrow0[kc];
            const int2 m1 = *(const int2*)&mrow1[kc];
            if (m0.x == 0) c[nf][0] = -1e8f;
            if (m0.y == 0) c[nf][1] = -1e8f;
            if (m1.x == 0) c[nf][2] = -1e8f;
            if (m1.y == 0) c[nf][3] = -1e8f;
        }

        // ---- online softmax on fragments ----
        float mx0 = -1e30f, mx1 = -1e30f;
#pragma unroll
        for (int nf = 0; nf < 8; nf++) {
            mx0 = fmaxf(mx0, fmaxf(c[nf][0], c[nf][1]));
            mx1 = fmaxf(mx1, fmaxf(c[nf][2], c[nf][3]));
        }
        mx0 = fmaxf(mx0, __shfl_xor_sync(0xffffffffu, mx0, 1));
        mx0 = fmaxf(mx0, __shfl_xor_sync(0xffffffffu, mx0, 2));
        mx1 = fmaxf(mx1, __shfl_xor_sync(0xffffffffu, mx1, 1));
        mx1 = fmaxf(mx1, __shfl_xor_sync(0xffffffffu, mx1, 2));

        const float mn0 = fmaxf(mi0, mx0);
        const float mn1 = fmaxf(mi1, mx1);
        const float al0 = __expf(mi0 - mn0);
        const float al1 = __expf(mi1 - mn1);

        float sum0 = 0.f, sum1 = 0.f;
#pragma unroll
        for (int nf = 0; nf < 8; nf++) {
            float e;
            e = __expf(c[nf][0] - mn0); sum0 += e; c[nf][0] = to_tf32(e);
            e = __expf(c[nf][1] - mn0); sum0 += e; c[nf][1] = to_tf32(e);
            e = __expf(c[nf][2] - mn1); sum1 += e; c[nf][2] = to_tf32(e);
            e = __expf(c[nf][3] - mn1); sum1 += e; c[nf][3] = to_tf32(e);
        }
        sum0 += __shfl_xor_sync(0xffffffffu, sum0, 1);
        sum0 += __shfl_xor_sync(0xffffffffu, sum0, 2);
        sum1 += __shfl_xor_sync(0xffffffffu, sum1, 1);
        sum1 += __shfl_xor_sync(0xffffffffu, sum1, 2);

        li0 = li0 * al0 + sum0;  mi0 = mn0;
        li1 = li1 * al1 + sum1;  mi1 = mn1;

#pragma unroll
        for (int nf = 0; nf < 8; nf++) {
            o[nf][0] *= al0; o[nf][1] *= al0;
            o[nf][2] *= al1; o[nf][3] *= al1;
        }

        // ---- PV: V row-major, B-fragment via 2 scalar LDS (conflict-free) ----
#pragma unroll
        for (int s = 0; s < 8; s++) {
            float a[4] = { c[s][0], c[s][2], c[s][1], c[s][3] };
            const int kr = s * 8 + 2 * qid;
#pragma unroll
            for (int nf = 0; nf < 8; nf++) {
                float bb[2];
                bb[0] = Vsb[kr * AST + nf * 8 + grp];
                bb[1] = Vsb[(kr + 1) * AST + nf * 8 + grp];
                mma_tf32(o[nf], a, bb);
            }
        }
    }

    // ---- finalize ----
    const float inv0 = 1.0f / li0;
    const float inv1 = 1.0f / li1;
    const size_t row0g = (size_t)(b * S_ + q0 + qrow0) * D_ + (size_t)h * HD_;
    const size_t row1g = row0g + (size_t)8 * D_;
#pragma unroll
    for (int nf = 0; nf < 8; nf++) {
        const int d0 = nf * 8 + 2 * qid;
        float2 v0, v1;
        v0.x = to_tf32(o[nf][0] * inv0); v0.y = to_tf32(o[nf][1] * inv0);
        v1.x = to_tf32(o[nf][2] * inv1); v1.y = to_tf32(o[nf][3] * inv1);
        *(float2*)&O[row0g + d0] = v0;
        *(float2*)&O[row1g + d0] = v1;
    }
}

// ---------------------------------------------------------------------------
// Launch.  Inputs: x, Wq, bq, Wk, bk, Wv, bv, W1, b1, W2, b2, mask
// ---------------------------------------------------------------------------
extern "C" void kernel_launch(void* const* d_in, const int* in_sizes, int n_in,
                              void* d_out, int out_size)
{
    const float* x    = (const float*)d_in[0];
    const float* Wq   = (const float*)d_in[1];
    const float* bq   = (const float*)d_in[2];
    const float* Wk   = (const float*)d_in[3];
    const float* bk   = (const float*)d_in[4];
    const float* Wv   = (const float*)d_in[5];
    const float* bv   = (const float*)d_in[6];
    const float* W1   = (const float*)d_in[7];
    const float* b1   = (const float*)d_in[8];
    const float* W2   = (const float*)d_in[9];
    const float* b2   = (const float*)d_in[10];
    const int*   mask = (const int*)d_in[11];
    float*       out  = (float*)d_out;

    float *Xp, *Wqkvp, *bqkvp, *W1p, *W2p, *QKVp, *Cp, *Hp;
    cudaGetSymbolAddress((void**)&Xp,    g_X);
    cudaGetSymbolAddress((void**)&Wqkvp, g_Wqkv);
    cudaGetSymbolAddress((void**)&bqkvp, g_bqkv);
    cudaGetSymbolAddress((void**)&W1p,   g_W1r);
    cudaGetSymbolAddress((void**)&W2p,   g_W2r);
    cudaGetSymbolAddress((void**)&QKVp,  g_QKV);
    cudaGetSymbolAddress((void**)&Cp,    g_C);
    cudaGetSymbolAddress((void**)&Hp,    g_Hid);

    cudaFuncSetAttribute(attn_tc,
                         cudaFuncAttributeMaxDynamicSharedMemorySize, ATTN_SMEM_BYTES);
    cudaFuncSetAttribute((const void*)gemm_tc<false, true, true>,
                         cudaFuncAttributeMaxDynamicSharedMemorySize, GEMM_SMEM_BYTES);
    cudaFuncSetAttribute((const void*)gemm_tc<true, true, false>,
                         cudaFuncAttributeMaxDynamicSharedMemorySize, GEMM_SMEM_BYTES);
    cudaFuncSetAttribute((const void*)gemm_tc<false, false, false>,
                         cudaFuncAttributeMaxDynamicSharedMemorySize, GEMM_SMEM_BYTES);

    const dim3 blk(256);

    // ---- prep: round inputs to tf32 once ----
    const int T = 256;
    round_copy4<<<(M_ * D_ / 4 + T - 1) / T, T>>>(x,  Xp,              M_ * D_ / 4);
    round_copy4<<<(D_ * D_ / 4 + T - 1) / T, T>>>(Wq, Wqkvp,           D_ * D_ / 4);
    round_copy4<<<(D_ * D_ / 4 + T - 1) / T, T>>>(Wk, Wqkvp + D_ * D_, D_ * D_ / 4);
    round_copy4<<<(D_ * D_ / 4 + T - 1) / T, T>>>(Wv, Wqkvp + 2 * D_ * D_, D_ * D_ / 4);
    round_copy4<<<(2 * D_ * D_ / 4 + T - 1) / T, T>>>(W1, W1p, 2 * D_ * D_ / 4);
    round_copy4<<<(2 * D_ * D_ / 4 + T - 1) / T, T>>>(W2, W2p, 2 * D_ * D_ / 4);
    concat_bias<<<(3 * D_ + T - 1) / T, T>>>(bq, bk, bv, bqkvp);

    // ---- fused QKV projection (epilogue: Q-scale + tf32 round) ----
    gemm_tc<false, true, true><<<dim3(3 * D_ / 128, M_ / 128), blk, GEMM_SMEM_BYTES>>>(
        Xp, Wqkvp, bqkvp, QKVp, M_, 3 * D_, D_);

    // ---- attention ----
    attn_tc<<<dim3(S_ / QT_, B_ * H_), blk, ATTN_SMEM_BYTES>>>(QKVp, mask, Cp);

    // ---- MLP ----
    gemm_tc<true, true, false><<<dim3(2 * D_ / 128, M_ / 128), blk, GEMM_SMEM_BYTES>>>(
        Cp, W1p, b1, Hp, M_, 2 * D_, D_);
    gemm_tc<false, false, false><<<dim3(D_ / 128, M_ / 128), blk, GEMM_SMEM_BYTES>>>(
        Hp, W2p, b2, out, M_, D_, 2 * D_);
}